// round 7
// baseline (speedup 1.0000x reference)
#include <cuda_runtime.h>
#include <cuda_bf16.h>
#include <cstdint>

#define NN   50000
#define INF  128
#define HF   256
#define NE   800000
#define KTOT 256

// ---------------- scratch (static device globals; no allocation) -------------
__device__ int   d_is64;
__device__ int   d_deg[NN];
__device__ int   d_rowptr[NN + 1];
__device__ int   d_cursor[NN];
__device__ int   d_csrc[NE];
__device__ __align__(16) __nv_bfloat16 d_Ahi[NN * KTOT];  // [agg1 | x] hi
__device__ __align__(16) __nv_bfloat16 d_Alo[NN * KTOT];  // [agg1 | x] lo
__device__ __align__(16) __nv_bfloat16 d_Whi[HF * KTOT];  // Wcat hi (n-major, k contig)
__device__ __align__(16) __nv_bfloat16 d_Wlo[HF * KTOT];  // Wcat lo
__device__ float d_p[NN];
__device__ float d_q[NN];

__device__ __forceinline__ int edge_at(const void* ei, long long idx) {
    if (d_is64) return (int)((const long long*)ei)[idx];
    return ((const int*)ei)[idx];
}

// ---------------- [1] init: zero deg + dtype detect + weight prep ------------
__global__ void k_init(const int* __restrict__ ei32,
                       const float* __restrict__ W1l, const float* __restrict__ W1r) {
    int t = blockIdx.x * blockDim.x + threadIdx.x;   // 65536 threads
    if (t == 0) {
        int all0 = 1;
        for (int i = 0; i < 32; i++)
            if (ei32[2 * i + 1] != 0) { all0 = 0; break; }
        d_is64 = all0;
    }
    if (t < NN) d_deg[t] = 0;
    if (t < HF * KTOT) {
        int n = t >> 8, k = t & 255;
        float w = (k < 128) ? W1l[n * 128 + k] : W1r[n * 128 + (k - 128)];
        __nv_bfloat16 h = __float2bfloat16(w);
        __nv_bfloat16 l = __float2bfloat16(w - __bfloat162float(h));
        d_Whi[t] = h;
        d_Wlo[t] = l;
    }
}

// ---------------- [2] count degrees ------------------------------------------
__global__ void k_count(const void* __restrict__ ei) {
    int e = blockIdx.x * blockDim.x + threadIdx.x;
    if (e < NE) {
        int dst = edge_at(ei, (long long)NE + e);
        if ((unsigned)dst < NN) atomicAdd(&d_deg[dst], 1);
    }
}

// ---------------- [3] single-block exclusive scan (1024 thr, 49 elems/thr) ---
__global__ void __launch_bounds__(1024, 1) k_scan() {
    __shared__ int wsum[32];
    int t = threadIdx.x;
    int lane = t & 31, wid = t >> 5;
    const int C = 49;           // 1024*49 = 50176 >= NN
    int beg = t * C;
    int end = beg + C < NN ? beg + C : NN;
    int s = 0;
    for (int i = beg; i < end; i++) s += d_deg[i];
    // warp inclusive scan
    int v = s;
#pragma unroll
    for (int off = 1; off < 32; off <<= 1) {
        int u = __shfl_up_sync(0xffffffffu, v, off);
        if (lane >= off) v += u;
    }
    if (lane == 31) wsum[wid] = v;
    __syncthreads();
    if (wid == 0) {
        int w = wsum[lane];
#pragma unroll
        for (int off = 1; off < 32; off <<= 1) {
            int u = __shfl_up_sync(0xffffffffu, w, off);
            if (lane >= off) w += u;
        }
        wsum[lane] = w;
        if (lane == 31) d_rowptr[NN] = w;   // total
    }
    __syncthreads();
    int base = (wid > 0 ? wsum[wid - 1] : 0) + (v - s);
    int run = base;
    for (int i = beg; i < end; i++) {
        d_rowptr[i] = run;
        d_cursor[i] = run;
        run += d_deg[i];
    }
}

// ---------------- [4] fill CSR -----------------------------------------------
__global__ void k_fill(const void* __restrict__ ei) {
    int e = blockIdx.x * blockDim.x + threadIdx.x;
    if (e < NE) {
        int dst = edge_at(ei, (long long)NE + e);
        int src = edge_at(ei, e);
        if ((unsigned)dst < NN && (unsigned)src < NN) {
            int pos = atomicAdd(&d_cursor[dst], 1);
            if ((unsigned)pos < NE) d_csrc[pos] = src;
        }
    }
}

// ---------------- bf16 hi/lo split helper ------------------------------------
__device__ __forceinline__ void cvt4(float4 v, uint2& hi, uint2& lo) {
    __nv_bfloat16 h0 = __float2bfloat16(v.x), h1 = __float2bfloat16(v.y),
                  h2 = __float2bfloat16(v.z), h3 = __float2bfloat16(v.w);
    __nv_bfloat16 l0 = __float2bfloat16(v.x - __bfloat162float(h0));
    __nv_bfloat16 l1 = __float2bfloat16(v.y - __bfloat162float(h1));
    __nv_bfloat16 l2 = __float2bfloat16(v.z - __bfloat162float(h2));
    __nv_bfloat16 l3 = __float2bfloat16(v.w - __bfloat162float(h3));
    hi.x = (uint32_t)__bfloat16_as_ushort(h0) | ((uint32_t)__bfloat16_as_ushort(h1) << 16);
    hi.y = (uint32_t)__bfloat16_as_ushort(h2) | ((uint32_t)__bfloat16_as_ushort(h3) << 16);
    lo.x = (uint32_t)__bfloat16_as_ushort(l0) | ((uint32_t)__bfloat16_as_ushort(l1) << 16);
    lo.y = (uint32_t)__bfloat16_as_ushort(l2) | ((uint32_t)__bfloat16_as_ushort(l3) << 16);
}

// ---------------- [5] aggregation 1 + pack A=[agg1|x] bf16 hi/lo -------------
__global__ void k_agg1(const float* __restrict__ x) {
    int warp = threadIdx.x >> 5;
    int lane = threadIdx.x & 31;
    int n = blockIdx.x * 8 + warp;
    if (n >= NN) return;

    int s = d_rowptr[n], e = d_rowptr[n + 1];
    float4 acc = make_float4(0.f, 0.f, 0.f, 0.f);
    for (int j = s; j < e; j++) {
        int src = d_csrc[j];
        float4 v = reinterpret_cast<const float4*>(x + (size_t)src * INF)[lane];
        acc.x += v.x; acc.y += v.y; acc.z += v.z; acc.w += v.w;
    }
    int deg = e - s;
    float inv = 1.f / (float)max(deg, 1);
    acc.x *= inv; acc.y *= inv; acc.z *= inv; acc.w *= inv;

    uint2 hi, lo;
    cvt4(acc, hi, lo);
    size_t rb = (size_t)n * KTOT;
    reinterpret_cast<uint2*>(d_Ahi + rb)[lane] = hi;
    reinterpret_cast<uint2*>(d_Alo + rb)[lane] = lo;
    float4 xv = reinterpret_cast<const float4*>(x + (size_t)n * INF)[lane];
    cvt4(xv, hi, lo);
    reinterpret_cast<uint2*>(d_Ahi + rb + 128)[lane] = hi;
    reinterpret_cast<uint2*>(d_Alo + rb + 128)[lane] = lo;
}

// ---------------- [6] mma.sync GEMM + fused p/q epilogue ---------------------
// BM=128, BN=256, K chunks of 64. 512 thr = 16 warps (8 M-stripes x 2 N-halves)
// bf16 3-term split. smem rows padded to 144B -> conflict-free ldmatrix.
#define SM_BIAS 0
#define SM_W2L  1024
#define SM_W2R  2048
#define SM_PQ   3072          // pbuf[2][128] + qbuf[2][128] = 2048 B
#define SM_AHI  5120          // 128*144 = 18432
#define SM_ALO  23552
#define SM_BHI  41984         // 256*144 = 36864
#define SM_BLO  78848
#define SM_TOT  115712

__device__ __forceinline__ uint32_t smem_u32(const void* p) {
    uint32_t a;
    asm("{ .reg .u64 t; cvta.to.shared.u64 t, %1; cvt.u32.u64 %0, t; }" : "=r"(a) : "l"(p));
    return a;
}
__device__ __forceinline__ void ldsm4(uint32_t& r0, uint32_t& r1, uint32_t& r2,
                                      uint32_t& r3, uint32_t addr) {
    asm volatile("ldmatrix.sync.aligned.m8n8.x4.shared.b16 {%0,%1,%2,%3}, [%4];"
                 : "=r"(r0), "=r"(r1), "=r"(r2), "=r"(r3) : "r"(addr));
}
__device__ __forceinline__ void mma16816(float* c, uint32_t a0, uint32_t a1,
                                         uint32_t a2, uint32_t a3,
                                         uint32_t b0, uint32_t b1) {
    asm volatile(
        "mma.sync.aligned.m16n8k16.row.col.f32.bf16.bf16.f32 "
        "{%0,%1,%2,%3},{%4,%5,%6,%7},{%8,%9},{%0,%1,%2,%3};"
        : "+f"(c[0]), "+f"(c[1]), "+f"(c[2]), "+f"(c[3])
        : "r"(a0), "r"(a1), "r"(a2), "r"(a3), "r"(b0), "r"(b1));
}

__global__ void __launch_bounds__(512, 1)
k_gemm(const float* __restrict__ b1, const float* __restrict__ W2l,
       const float* __restrict__ W2r) {
    extern __shared__ char smem[];
    uint32_t sb = smem_u32(smem);
    int t = threadIdx.x;
    int wid = t >> 5;
    int lane = t & 31;
    int g = lane >> 2;        // 0..7
    int tq = lane & 3;        // 0..3
    int wm = wid & 7;         // M stripe (16 rows)
    int wn = wid >> 3;        // N half (128 cols)
    int rowbase = blockIdx.x * 128;

    if (t < 256) {
        *reinterpret_cast<float*>(smem + SM_BIAS + t * 4) = b1[t];
        *reinterpret_cast<float*>(smem + SM_W2L + t * 4) = W2l[t];
        *reinterpret_cast<float*>(smem + SM_W2R + t * 4) = W2r[t];
    }

    float acc[64];
#pragma unroll
    for (int i = 0; i < 64; i++) acc[i] = 0.f;

    // ldmatrix source addresses (fixed per thread, offset by ks)
    int arow = wm * 16 + (lane & 15);
    uint32_t a_off = (uint32_t)(arow * 144 + ((lane >> 4) & 1) * 16);
    int bro = (lane >> 4) & 1;
    uint32_t b_off = (uint32_t)(((lane & 7) + bro * 8) * 144 + ((lane >> 3) & 1) * 16);

    for (int ch = 0; ch < 4; ch++) {
        int kbase = ch * 64;
        __syncthreads();
        // stage A chunk: 128 rows x 64k hi+lo (1024 uint4 each)
#pragma unroll
        for (int i = 0; i < 2; i++) {
            int v = t + i * 512;
            int row = v >> 3, kg = v & 7;
            int gr = rowbase + row;
            uint4 z = make_uint4(0, 0, 0, 0);
            uint4 a = (gr < NN)
                ? *reinterpret_cast<const uint4*>(d_Ahi + (size_t)gr * KTOT + kbase + kg * 8) : z;
            *reinterpret_cast<uint4*>(smem + SM_AHI + row * 144 + kg * 16) = a;
            uint4 b = (gr < NN)
                ? *reinterpret_cast<const uint4*>(d_Alo + (size_t)gr * KTOT + kbase + kg * 8) : z;
            *reinterpret_cast<uint4*>(smem + SM_ALO + row * 144 + kg * 16) = b;
        }
        // stage B chunk: 256 rows x 64k hi+lo (2048 uint4 each)
#pragma unroll
        for (int i = 0; i < 4; i++) {
            int v = t + i * 512;
            int row = v >> 3, kg = v & 7;
            uint4 a = *reinterpret_cast<const uint4*>(d_Whi + (size_t)row * KTOT + kbase + kg * 8);
            *reinterpret_cast<uint4*>(smem + SM_BHI + row * 144 + kg * 16) = a;
            uint4 b = *reinterpret_cast<const uint4*>(d_Wlo + (size_t)row * KTOT + kbase + kg * 8);
            *reinterpret_cast<uint4*>(smem + SM_BLO + row * 144 + kg * 16) = b;
        }
        __syncthreads();

#pragma unroll
        for (int ks = 0; ks < 4; ks++) {
            uint32_t ksb = (uint32_t)(ks * 32);
            uint32_t ah0, ah1, ah2, ah3, al0, al1, al2, al3;
            ldsm4(ah0, ah1, ah2, ah3, sb + SM_AHI + a_off + ksb);
            ldsm4(al0, al1, al2, al3, sb + SM_ALO + a_off + ksb);
#pragma unroll
            for (int jp = 0; jp < 8; jp++) {
                uint32_t brow = (uint32_t)((wn * 128 + jp * 16) * 144);
                uint32_t bh0, bh1, bh2, bh3, bl0, bl1, bl2, bl3;
                ldsm4(bh0, bh1, bh2, bh3, sb + SM_BHI + brow + b_off + ksb);
                ldsm4(bl0, bl1, bl2, bl3, sb + SM_BLO + brow + b_off + ksb);
                float* c0 = acc + jp * 8;
                float* c1 = acc + jp * 8 + 4;
                mma16816(c0, ah0, ah1, ah2, ah3, bh0, bh1);
                mma16816(c0, ah0, ah1, ah2, ah3, bl0, bl1);
                mma16816(c0, al0, al1, al2, al3, bh0, bh1);
                mma16816(c1, ah0, ah1, ah2, ah3, bh2, bh3);
                mma16816(c1, ah0, ah1, ah2, ah3, bl2, bl3);
                mma16816(c1, al0, al1, al2, al3, bh2, bh3);
            }
        }
    }
    __syncthreads();

    // fused epilogue: relu(acc + bias), dot with W2l/W2r
    const float* s_bias = reinterpret_cast<const float*>(smem + SM_BIAS);
    const float* s_w2l = reinterpret_cast<const float*>(smem + SM_W2L);
    const float* s_w2r = reinterpret_cast<const float*>(smem + SM_W2R);
    float p1 = 0.f, q1 = 0.f, p2 = 0.f, q2 = 0.f;
#pragma unroll
    for (int j = 0; j < 16; j++) {
        int c0 = wn * 128 + j * 8 + 2 * tq;
        float v00 = acc[j * 4 + 0] + s_bias[c0];
        float v01 = acc[j * 4 + 1] + s_bias[c0 + 1];
        float v10 = acc[j * 4 + 2] + s_bias[c0];
        float v11 = acc[j * 4 + 3] + s_bias[c0 + 1];
        v00 = v00 > 0.f ? v00 : 0.f;
        v01 = v01 > 0.f ? v01 : 0.f;
        v10 = v10 > 0.f ? v10 : 0.f;
        v11 = v11 > 0.f ? v11 : 0.f;
        p1 = fmaf(v00, s_w2l[c0], fmaf(v01, s_w2l[c0 + 1], p1));
        q1 = fmaf(v00, s_w2r[c0], fmaf(v01, s_w2r[c0 + 1], q1));
        p2 = fmaf(v10, s_w2l[c0], fmaf(v11, s_w2l[c0 + 1], p2));
        q2 = fmaf(v10, s_w2r[c0], fmaf(v11, s_w2r[c0 + 1], q2));
    }
#pragma unroll
    for (int off = 1; off < 4; off <<= 1) {
        p1 += __shfl_xor_sync(0xffffffffu, p1, off);
        q1 += __shfl_xor_sync(0xffffffffu, q1, off);
        p2 += __shfl_xor_sync(0xffffffffu, p2, off);
        q2 += __shfl_xor_sync(0xffffffffu, q2, off);
    }
    float* pbuf = reinterpret_cast<float*>(smem + SM_PQ);           // [2][128]
    float* qbuf = reinterpret_cast<float*>(smem + SM_PQ + 1024);    // [2][128]
    if (tq == 0) {
        int r1 = wm * 16 + g;
        pbuf[wn * 128 + r1] = p1;
        qbuf[wn * 128 + r1] = q1;
        pbuf[wn * 128 + r1 + 8] = p2;
        qbuf[wn * 128 + r1 + 8] = q2;
    }
    __syncthreads();
    if (t < 128) {
        int gr = rowbase + t;
        if (gr < NN) {
            d_p[gr] = pbuf[t] + pbuf[128 + t];
            d_q[gr] = qbuf[t] + qbuf[128 + t];
        }
    }
}

// ---------------- [7] out = mean_agg(p) + b2 + q -----------------------------
__global__ void k_out(const float* __restrict__ b2, float* __restrict__ out) {
    int warp = threadIdx.x >> 5;
    int lane = threadIdx.x & 31;
    int n = blockIdx.x * 8 + warp;
    if (n >= NN) return;

    int s = d_rowptr[n], e = d_rowptr[n + 1];
    float acc = 0.f;
    for (int j = s + lane; j < e; j += 32) acc += d_p[d_csrc[j]];
#pragma unroll
    for (int off = 16; off > 0; off >>= 1)
        acc += __shfl_down_sync(0xffffffffu, acc, off);
    if (lane == 0) {
        int deg = e - s;
        out[n] = acc / (float)max(deg, 1) + b2[0] + d_q[n];
    }
}

// ---------------- launch -----------------------------------------------------
extern "C" void kernel_launch(void* const* d_in, const int* in_sizes, int n_in,
                              void* d_out, int out_size) {
    const float* x    = (const float*)d_in[0];
    const void*  ei   = d_in[1];
    const float* W1l  = (const float*)d_in[2];
    const float* b1   = (const float*)d_in[3];
    const float* W1r  = (const float*)d_in[4];
    const float* W2l  = (const float*)d_in[5];
    const float* b2   = (const float*)d_in[6];
    const float* W2r  = (const float*)d_in[7];
    float* out = (float*)d_out;

    static int attr_set = 0;
    if (!attr_set) {
        cudaFuncSetAttribute(k_gemm, cudaFuncAttributeMaxDynamicSharedMemorySize, SM_TOT);
        attr_set = 1;
    }

    k_init<<<(HF * KTOT + 255) / 256, 256>>>((const int*)ei, W1l, W1r);
    k_count<<<(NE + 255) / 256, 256>>>(ei);
    k_scan<<<1, 1024>>>();
    k_fill<<<(NE + 255) / 256, 256>>>(ei);
    k_agg1<<<(NN + 7) / 8, 256>>>(x);
    k_gemm<<<(NN + 127) / 128, 512, SM_TOT>>>(b1, W2l, W2r);
    k_out<<<(NN + 7) / 8, 256>>>(b2, out);
}

// round 9
// speedup vs baseline: 1.0002x; 1.0002x over previous
#include <cuda_runtime.h>
#include <cuda_bf16.h>
#include <cstdint>

#define NN   50000
#define INF  128
#define HF   256
#define NE   800000
#define KTOT 256

// ---------------- scratch (static device globals; no allocation) -------------
__device__ int   d_is64;
__device__ int   d_deg[NN];
__device__ int   d_rowptr[NN + 1];
__device__ int   d_cursor[NN];
__device__ int   d_csrc[NE];
__device__ __align__(16) __nv_bfloat16 d_Ahi[NN * KTOT];  // [agg1 | x] hi
__device__ __align__(16) __nv_bfloat16 d_Alo[NN * KTOT];  // [agg1 | x] lo
__device__ __align__(16) __nv_bfloat16 d_Whi[HF * KTOT];  // Wcat hi (n-major, k contig)
__device__ __align__(16) __nv_bfloat16 d_Wlo[HF * KTOT];  // Wcat lo
__device__ float d_p[NN];
__device__ float d_q[NN];

__device__ __forceinline__ int edge_at(const void* ei, long long idx) {
    if (d_is64) return (int)((const long long*)ei)[idx];
    return ((const int*)ei)[idx];
}

// ---------------- [1] init: zero deg + dtype detect + weight prep ------------
__global__ void k_init(const int* __restrict__ ei32,
                       const float* __restrict__ W1l, const float* __restrict__ W1r) {
    int t = blockIdx.x * blockDim.x + threadIdx.x;   // 65536 threads
    if (t == 0) {
        int all0 = 1;
        for (int i = 0; i < 32; i++)
            if (ei32[2 * i + 1] != 0) { all0 = 0; break; }
        d_is64 = all0;
    }
    if (t < NN) d_deg[t] = 0;
    if (t < HF * KTOT) {
        int n = t >> 8, k = t & 255;
        float w = (k < 128) ? W1l[n * 128 + k] : W1r[n * 128 + (k - 128)];
        __nv_bfloat16 h = __float2bfloat16(w);
        __nv_bfloat16 l = __float2bfloat16(w - __bfloat162float(h));
        d_Whi[t] = h;
        d_Wlo[t] = l;
    }
}

// ---------------- [2] count degrees ------------------------------------------
__global__ void k_count(const void* __restrict__ ei) {
    int e = blockIdx.x * blockDim.x + threadIdx.x;
    if (e < NE) {
        int dst = edge_at(ei, (long long)NE + e);
        if ((unsigned)dst < NN) atomicAdd(&d_deg[dst], 1);
    }
}

// ---------------- [3] single-block exclusive scan ----------------------------
__global__ void __launch_bounds__(1024, 1) k_scan() {
    __shared__ int wsum[32];
    int t = threadIdx.x;
    int lane = t & 31, wid = t >> 5;
    const int C = 49;           // 1024*49 = 50176 >= NN
    int beg = t * C;
    int end = beg + C < NN ? beg + C : NN;
    int s = 0;
    for (int i = beg; i < end; i++) s += d_deg[i];
    int v = s;
#pragma unroll
    for (int off = 1; off < 32; off <<= 1) {
        int u = __shfl_up_sync(0xffffffffu, v, off);
        if (lane >= off) v += u;
    }
    if (lane == 31) wsum[wid] = v;
    __syncthreads();
    if (wid == 0) {
        int w = wsum[lane];
#pragma unroll
        for (int off = 1; off < 32; off <<= 1) {
            int u = __shfl_up_sync(0xffffffffu, w, off);
            if (lane >= off) w += u;
        }
        wsum[lane] = w;
        if (lane == 31) d_rowptr[NN] = w;
    }
    __syncthreads();
    int base = (wid > 0 ? wsum[wid - 1] : 0) + (v - s);
    int run = base;
    for (int i = beg; i < end; i++) {
        d_rowptr[i] = run;
        d_cursor[i] = run;
        run += d_deg[i];
    }
}

// ---------------- [4] fill CSR -----------------------------------------------
__global__ void k_fill(const void* __restrict__ ei) {
    int e = blockIdx.x * blockDim.x + threadIdx.x;
    if (e < NE) {
        int dst = edge_at(ei, (long long)NE + e);
        int src = edge_at(ei, e);
        if ((unsigned)dst < NN && (unsigned)src < NN) {
            int pos = atomicAdd(&d_cursor[dst], 1);
            if ((unsigned)pos < NE) d_csrc[pos] = src;
        }
    }
}

// ---------------- bf16 hi/lo split helper ------------------------------------
__device__ __forceinline__ void cvt4(float4 v, uint2& hi, uint2& lo) {
    __nv_bfloat16 h0 = __float2bfloat16(v.x), h1 = __float2bfloat16(v.y),
                  h2 = __float2bfloat16(v.z), h3 = __float2bfloat16(v.w);
    __nv_bfloat16 l0 = __float2bfloat16(v.x - __bfloat162float(h0));
    __nv_bfloat16 l1 = __float2bfloat16(v.y - __bfloat162float(h1));
    __nv_bfloat16 l2 = __float2bfloat16(v.z - __bfloat162float(h2));
    __nv_bfloat16 l3 = __float2bfloat16(v.w - __bfloat162float(h3));
    hi.x = (uint32_t)__bfloat16_as_ushort(h0) | ((uint32_t)__bfloat16_as_ushort(h1) << 16);
    hi.y = (uint32_t)__bfloat16_as_ushort(h2) | ((uint32_t)__bfloat16_as_ushort(h3) << 16);
    lo.x = (uint32_t)__bfloat16_as_ushort(l0) | ((uint32_t)__bfloat16_as_ushort(l1) << 16);
    lo.y = (uint32_t)__bfloat16_as_ushort(l2) | ((uint32_t)__bfloat16_as_ushort(l3) << 16);
}

// ---------------- [5] aggregation 1 + pack A=[agg1|x] bf16 hi/lo -------------
__global__ void k_agg1(const float* __restrict__ x) {
    int warp = threadIdx.x >> 5;
    int lane = threadIdx.x & 31;
    int n = blockIdx.x * 8 + warp;
    if (n >= NN) return;

    int s = d_rowptr[n], e = d_rowptr[n + 1];
    float4 acc = make_float4(0.f, 0.f, 0.f, 0.f);
    for (int j = s; j < e; j++) {
        int src = d_csrc[j];
        float4 v = reinterpret_cast<const float4*>(x + (size_t)src * INF)[lane];
        acc.x += v.x; acc.y += v.y; acc.z += v.z; acc.w += v.w;
    }
    int deg = e - s;
    float inv = 1.f / (float)max(deg, 1);
    acc.x *= inv; acc.y *= inv; acc.z *= inv; acc.w *= inv;

    uint2 hi, lo;
    cvt4(acc, hi, lo);
    size_t rb = (size_t)n * KTOT;
    reinterpret_cast<uint2*>(d_Ahi + rb)[lane] = hi;
    reinterpret_cast<uint2*>(d_Alo + rb)[lane] = lo;
    float4 xv = reinterpret_cast<const float4*>(x + (size_t)n * INF)[lane];
    cvt4(xv, hi, lo);
    reinterpret_cast<uint2*>(d_Ahi + rb + 128)[lane] = hi;
    reinterpret_cast<uint2*>(d_Alo + rb + 128)[lane] = lo;
}

// ---------------- [6] mma.sync GEMM + fused p/q epilogue ---------------------
// BM=64, BN=256, K chunks of 64. 256 thr = 8 warps (4 M-stripes x 2 N-halves).
// 2 CTAs/SM for load/MMA overlap. ldmatrix fragment loads, 144B row pitch.
// bf16 3-term split: Ahi*Bhi + Ahi*Blo + Alo*Bhi.
#define SM_BIAS 0
#define SM_W2L  1024
#define SM_W2R  2048
#define SM_PQ   3072          // pbuf[2][64] + qbuf[2][64] = 1024 B
#define SM_AHI  4096          // 64*144 = 9216
#define SM_ALO  13312
#define SM_BHI  22528         // 256*144 = 36864
#define SM_BLO  59392
#define SM_TOT  96256

__device__ __forceinline__ uint32_t smem_u32(const void* p) {
    uint32_t a;
    asm("{ .reg .u64 t; cvta.to.shared.u64 t, %1; cvt.u32.u64 %0, t; }" : "=r"(a) : "l"(p));
    return a;
}
__device__ __forceinline__ void ldsm4(uint32_t& r0, uint32_t& r1, uint32_t& r2,
                                      uint32_t& r3, uint32_t addr) {
    asm volatile("ldmatrix.sync.aligned.m8n8.x4.shared.b16 {%0,%1,%2,%3}, [%4];"
                 : "=r"(r0), "=r"(r1), "=r"(r2), "=r"(r3) : "r"(addr));
}
__device__ __forceinline__ void mma16816(float* c, uint32_t a0, uint32_t a1,
                                         uint32_t a2, uint32_t a3,
                                         uint32_t b0, uint32_t b1) {
    asm volatile(
        "mma.sync.aligned.m16n8k16.row.col.f32.bf16.bf16.f32 "
        "{%0,%1,%2,%3},{%4,%5,%6,%7},{%8,%9},{%0,%1,%2,%3};"
        : "+f"(c[0]), "+f"(c[1]), "+f"(c[2]), "+f"(c[3])
        : "r"(a0), "r"(a1), "r"(a2), "r"(a3), "r"(b0), "r"(b1));
}

__global__ void __launch_bounds__(256, 2)
k_gemm(const float* __restrict__ b1, const float* __restrict__ W2l,
       const float* __restrict__ W2r) {
    extern __shared__ char smem[];
    uint32_t sb = smem_u32(smem);
    int t = threadIdx.x;
    int wid = t >> 5;
    int lane = t & 31;
    int g = lane >> 2;        // 0..7
    int tq = lane & 3;        // 0..3
    int wm = wid & 3;         // M stripe (16 rows of 64)
    int wn = wid >> 2;        // N half (128 cols)
    int rowbase = blockIdx.x * 64;

    *reinterpret_cast<float*>(smem + SM_BIAS + t * 4) = b1[t];
    *reinterpret_cast<float*>(smem + SM_W2L + t * 4) = W2l[t];
    *reinterpret_cast<float*>(smem + SM_W2R + t * 4) = W2r[t];

    float acc[64];
#pragma unroll
    for (int i = 0; i < 64; i++) acc[i] = 0.f;

    // ldmatrix per-thread source addresses (fixed; + ks*32 at use)
    int arow = wm * 16 + (lane & 15);
    uint32_t a_off = (uint32_t)(arow * 144 + ((lane >> 4) & 1) * 16);
    int bro = (lane >> 4) & 1;
    uint32_t b_off = (uint32_t)(((lane & 7) + bro * 8) * 144 + ((lane >> 3) & 1) * 16);

    for (int ch = 0; ch < 4; ch++) {
        int kbase = ch * 64;
        __syncthreads();
        // stage A chunk: 64 rows x 64k hi+lo (512 uint4 each -> 2/thread each)
#pragma unroll
        for (int i = 0; i < 2; i++) {
            int v = t + i * 256;
            int row = v >> 3, kg = v & 7;
            int gr = rowbase + row;
            uint4 z = make_uint4(0, 0, 0, 0);
            uint4 a = (gr < NN)
                ? *reinterpret_cast<const uint4*>(d_Ahi + (size_t)gr * KTOT + kbase + kg * 8) : z;
            *reinterpret_cast<uint4*>(smem + SM_AHI + row * 144 + kg * 16) = a;
            uint4 b = (gr < NN)
                ? *reinterpret_cast<const uint4*>(d_Alo + (size_t)gr * KTOT + kbase + kg * 8) : z;
            *reinterpret_cast<uint4*>(smem + SM_ALO + row * 144 + kg * 16) = b;
        }
        // stage B chunk: 256 rows x 64k hi+lo (2048 uint4 each -> 8/thread each)
#pragma unroll
        for (int i = 0; i < 8; i++) {
            int v = t + i * 256;
            int row = v >> 3, kg = v & 7;
            uint4 a = *reinterpret_cast<const uint4*>(d_Whi + (size_t)row * KTOT + kbase + kg * 8);
            *reinterpret_cast<uint4*>(smem + SM_BHI + row * 144 + kg * 16) = a;
            uint4 b = *reinterpret_cast<const uint4*>(d_Wlo + (size_t)row * KTOT + kbase + kg * 8);
            *reinterpret_cast<uint4*>(smem + SM_BLO + row * 144 + kg * 16) = b;
        }
        __syncthreads();

#pragma unroll
        for (int ks = 0; ks < 4; ks++) {
            uint32_t ksb = (uint32_t)(ks * 32);
            uint32_t ah0, ah1, ah2, ah3, al0, al1, al2, al3;
            ldsm4(ah0, ah1, ah2, ah3, sb + SM_AHI + a_off + ksb);
            ldsm4(al0, al1, al2, al3, sb + SM_ALO + a_off + ksb);
#pragma unroll
            for (int jp = 0; jp < 8; jp++) {
                uint32_t brow = (uint32_t)((wn * 128 + jp * 16) * 144);
                uint32_t bh0, bh1, bh2, bh3, bl0, bl1, bl2, bl3;
                ldsm4(bh0, bh1, bh2, bh3, sb + SM_BHI + brow + b_off + ksb);
                ldsm4(bl0, bl1, bl2, bl3, sb + SM_BLO + brow + b_off + ksb);
                float* c0 = acc + jp * 8;
                float* c1 = acc + jp * 8 + 4;
                mma16816(c0, ah0, ah1, ah2, ah3, bh0, bh1);
                mma16816(c0, ah0, ah1, ah2, ah3, bl0, bl1);
                mma16816(c0, al0, al1, al2, al3, bh0, bh1);
                mma16816(c1, ah0, ah1, ah2, ah3, bh2, bh3);
                mma16816(c1, ah0, ah1, ah2, ah3, bl2, bl3);
                mma16816(c1, al0, al1, al2, al3, bh2, bh3);
            }
        }
    }
    __syncthreads();

    // fused epilogue: relu(acc + bias), dot with W2l/W2r
    const float* s_bias = reinterpret_cast<const float*>(smem + SM_BIAS);
    const float* s_w2l = reinterpret_cast<const float*>(smem + SM_W2L);
    const float* s_w2r = reinterpret_cast<const float*>(smem + SM_W2R);
    float p1 = 0.f, q1 = 0.f, p2 = 0.f, q2 = 0.f;
#pragma unroll
    for (int j = 0; j < 16; j++) {
        int c0 = wn * 128 + j * 8 + 2 * tq;
        float v00 = acc[j * 4 + 0] + s_bias[c0];
        float v01 = acc[j * 4 + 1] + s_bias[c0 + 1];
        float v10 = acc[j * 4 + 2] + s_bias[c0];
        float v11 = acc[j * 4 + 3] + s_bias[c0 + 1];
        v00 = v00 > 0.f ? v00 : 0.f;
        v01 = v01 > 0.f ? v01 : 0.f;
        v10 = v10 > 0.f ? v10 : 0.f;
        v11 = v11 > 0.f ? v11 : 0.f;
        p1 = fmaf(v00, s_w2l[c0], fmaf(v01, s_w2l[c0 + 1], p1));
        q1 = fmaf(v00, s_w2r[c0], fmaf(v01, s_w2r[c0 + 1], q1));
        p2 = fmaf(v10, s_w2l[c0], fmaf(v11, s_w2l[c0 + 1], p2));
        q2 = fmaf(v10, s_w2r[c0], fmaf(v11, s_w2r[c0 + 1], q2));
    }
#pragma unroll
    for (int off = 1; off < 4; off <<= 1) {
        p1 += __shfl_xor_sync(0xffffffffu, p1, off);
        q1 += __shfl_xor_sync(0xffffffffu, q1, off);
        p2 += __shfl_xor_sync(0xffffffffu, p2, off);
        q2 += __shfl_xor_sync(0xffffffffu, q2, off);
    }
    float* pbuf = reinterpret_cast<float*>(smem + SM_PQ);          // [2][64]
    float* qbuf = reinterpret_cast<float*>(smem + SM_PQ + 512);    // [2][64]
    if (tq == 0) {
        int r1 = wm * 16 + g;
        pbuf[wn * 64 + r1] = p1;
        qbuf[wn * 64 + r1] = q1;
        pbuf[wn * 64 + r1 + 8] = p2;
        qbuf[wn * 64 + r1 + 8] = q2;
    }
    __syncthreads();
    if (t < 64) {
        int gr = rowbase + t;
        if (gr < NN) {
            d_p[gr] = pbuf[t] + pbuf[64 + t];
            d_q[gr] = qbuf[t] + qbuf[64 + t];
        }
    }
}

// ---------------- [7] out = mean_agg(p) + b2 + q -----------------------------
__global__ void k_out(const float* __restrict__ b2, float* __restrict__ out) {
    int warp = threadIdx.x >> 5;
    int lane = threadIdx.x & 31;
    int n = blockIdx.x * 8 + warp;
    if (n >= NN) return;

    int s = d_rowptr[n], e = d_rowptr[n + 1];
    float acc = 0.f;
    for (int j = s + lane; j < e; j += 32) acc += d_p[d_csrc[j]];
#pragma unroll
    for (int off = 16; off > 0; off >>= 1)
        acc += __shfl_down_sync(0xffffffffu, acc, off);
    if (lane == 0) {
        int deg = e - s;
        out[n] = acc / (float)max(deg, 1) + b2[0] + d_q[n];
    }
}

// ---------------- launch -----------------------------------------------------
extern "C" void kernel_launch(void* const* d_in, const int* in_sizes, int n_in,
                              void* d_out, int out_size) {
    const float* x    = (const float*)d_in[0];
    const void*  ei   = d_in[1];
    const float* W1l  = (const float*)d_in[2];
    const float* b1   = (const float*)d_in[3];
    const float* W1r  = (const float*)d_in[4];
    const float* W2l  = (const float*)d_in[5];
    const float* b2   = (const float*)d_in[6];
    const float* W2r  = (const float*)d_in[7];
    float* out = (float*)d_out;

    static int attr_set = 0;
    if (!attr_set) {
        cudaFuncSetAttribute(k_gemm, cudaFuncAttributeMaxDynamicSharedMemorySize, SM_TOT);
        attr_set = 1;
    }

    k_init<<<(HF * KTOT + 255) / 256, 256>>>((const int*)ei, W1l, W1r);
    k_count<<<(NE + 255) / 256, 256>>>(ei);
    k_scan<<<1, 1024>>>();
    k_fill<<<(NE + 255) / 256, 256>>>(ei);
    k_agg1<<<(NN + 7) / 8, 256>>>(x);
    k_gemm<<<(NN + 63) / 64, 256, SM_TOT>>>(b1, W2l, W2r);
    k_out<<<(NN + 7) / 8, 256>>>(b2, out);
}

// round 10
// speedup vs baseline: 1.4925x; 1.4923x over previous
#include <cuda_runtime.h>
#include <cuda_bf16.h>
#include <cstdint>

#define NN   50000
#define INF  128
#define HF   256
#define NE   800000
#define KTOT 256

// ---------------- scratch (static device globals; no allocation) -------------
__device__ int   d_is64;
__device__ int   d_deg[NN];
__device__ int   d_rowptr[NN + 1];
__device__ int   d_cursor[NN];
__device__ int   d_csrc[NE];
__device__ __align__(16) __nv_bfloat16 d_Ahi[NN * KTOT];  // [agg1 | x] hi
__device__ __align__(16) __nv_bfloat16 d_Alo[NN * KTOT];  // [agg1 | x] lo
__device__ __align__(16) __nv_bfloat16 d_Whi[HF * KTOT];  // Wcat hi (n-major, k contig)
__device__ __align__(16) __nv_bfloat16 d_Wlo[HF * KTOT];  // Wcat lo
__device__ float d_p[NN];
__device__ float d_q[NN];
__device__ int   d_bsum[64];
__device__ int   d_boff[64];

__device__ __forceinline__ int edge_at(const void* ei, long long idx) {
    if (d_is64) return (int)((const long long*)ei)[idx];
    return ((const int*)ei)[idx];
}

// ---------------- [1] init: zero deg + dtype detect + weight prep ------------
__global__ void k_init(const int* __restrict__ ei32,
                       const float* __restrict__ W1l, const float* __restrict__ W1r) {
    int t = blockIdx.x * blockDim.x + threadIdx.x;   // 65536 threads
    if (t == 0) {
        int all0 = 1;
        for (int i = 0; i < 32; i++)
            if (ei32[2 * i + 1] != 0) { all0 = 0; break; }
        d_is64 = all0;
    }
    if (t < NN) d_deg[t] = 0;
    if (t < HF * KTOT) {
        int n = t >> 8, k = t & 255;
        float w = (k < 128) ? W1l[n * 128 + k] : W1r[n * 128 + (k - 128)];
        __nv_bfloat16 h = __float2bfloat16(w);
        __nv_bfloat16 l = __float2bfloat16(w - __bfloat162float(h));
        d_Whi[t] = h;
        d_Wlo[t] = l;
    }
}

// ---------------- [2] count degrees ------------------------------------------
__global__ void k_count(const void* __restrict__ ei) {
    int e = blockIdx.x * blockDim.x + threadIdx.x;
    if (e < NE) {
        int dst = edge_at(ei, (long long)NE + e);
        if ((unsigned)dst < NN) atomicAdd(&d_deg[dst], 1);
    }
}

// ---------------- [3-5] grid-wide exclusive scan (proven R4 version) ---------
__global__ void k_scan1() {
    __shared__ int sh[256];
    int t = threadIdx.x;
    int base = blockIdx.x * 1024 + t * 4;
    int v[4];
#pragma unroll
    for (int i = 0; i < 4; i++) {
        int idx = base + i;
        v[i] = (idx < NN) ? d_deg[idx] : 0;
    }
    int s = v[0] + v[1] + v[2] + v[3];
    sh[t] = s;
    __syncthreads();
    for (int off = 1; off < 256; off <<= 1) {
        int x_ = (t >= off) ? sh[t - off] : 0;
        __syncthreads();
        sh[t] += x_;
        __syncthreads();
    }
    int run = sh[t] - s;
#pragma unroll
    for (int i = 0; i < 4; i++) {
        int idx = base + i;
        if (idx < NN) d_rowptr[idx] = run;
        run += v[i];
    }
    if (t == 255) d_bsum[blockIdx.x] = sh[255];
}
__global__ void k_scan2(int nb) {
    if (threadIdx.x == 0) {
        int run = 0;
        for (int b = 0; b < nb; b++) { d_boff[b] = run; run += d_bsum[b]; }
    }
}
__global__ void k_scan3() {
    int i = blockIdx.x * blockDim.x + threadIdx.x;
    if (i < NN) {
        int r = d_rowptr[i] + d_boff[i >> 10];
        d_rowptr[i] = r;
        d_cursor[i] = r;
    }
    if (i == 0) d_rowptr[NN] = NE;
}

// ---------------- [6] fill CSR -----------------------------------------------
__global__ void k_fill(const void* __restrict__ ei) {
    int e = blockIdx.x * blockDim.x + threadIdx.x;
    if (e < NE) {
        int dst = edge_at(ei, (long long)NE + e);
        int src = edge_at(ei, e);
        if ((unsigned)dst < NN && (unsigned)src < NN) {
            int pos = atomicAdd(&d_cursor[dst], 1);
            if ((unsigned)pos < NE) d_csrc[pos] = src;
        }
    }
}

// ---------------- bf16 hi/lo split helper ------------------------------------
__device__ __forceinline__ void cvt4(float4 v, uint2& hi, uint2& lo) {
    __nv_bfloat16 h0 = __float2bfloat16(v.x), h1 = __float2bfloat16(v.y),
                  h2 = __float2bfloat16(v.z), h3 = __float2bfloat16(v.w);
    __nv_bfloat16 l0 = __float2bfloat16(v.x - __bfloat162float(h0));
    __nv_bfloat16 l1 = __float2bfloat16(v.y - __bfloat162float(h1));
    __nv_bfloat16 l2 = __float2bfloat16(v.z - __bfloat162float(h2));
    __nv_bfloat16 l3 = __float2bfloat16(v.w - __bfloat162float(h3));
    hi.x = (uint32_t)__bfloat16_as_ushort(h0) | ((uint32_t)__bfloat16_as_ushort(h1) << 16);
    hi.y = (uint32_t)__bfloat16_as_ushort(h2) | ((uint32_t)__bfloat16_as_ushort(h3) << 16);
    lo.x = (uint32_t)__bfloat16_as_ushort(l0) | ((uint32_t)__bfloat16_as_ushort(l1) << 16);
    lo.y = (uint32_t)__bfloat16_as_ushort(l2) | ((uint32_t)__bfloat16_as_ushort(l3) << 16);
}

// ---------------- [7] aggregation 1 + pack A=[agg1|x] bf16 hi/lo -------------
__global__ void k_agg1(const float* __restrict__ x) {
    int warp = threadIdx.x >> 5;
    int lane = threadIdx.x & 31;
    int n = blockIdx.x * 8 + warp;
    if (n >= NN) return;

    int s = d_rowptr[n], e = d_rowptr[n + 1];
    float4 acc = make_float4(0.f, 0.f, 0.f, 0.f);
    for (int j = s; j < e; j++) {
        int src = d_csrc[j];
        float4 v = reinterpret_cast<const float4*>(x + (size_t)src * INF)[lane];
        acc.x += v.x; acc.y += v.y; acc.z += v.z; acc.w += v.w;
    }
    int deg = e - s;
    float inv = 1.f / (float)max(deg, 1);
    acc.x *= inv; acc.y *= inv; acc.z *= inv; acc.w *= inv;

    uint2 hi, lo;
    cvt4(acc, hi, lo);
    size_t rb = (size_t)n * KTOT;
    reinterpret_cast<uint2*>(d_Ahi + rb)[lane] = hi;
    reinterpret_cast<uint2*>(d_Alo + rb)[lane] = lo;
    float4 xv = reinterpret_cast<const float4*>(x + (size_t)n * INF)[lane];
    cvt4(xv, hi, lo);
    reinterpret_cast<uint2*>(d_Ahi + rb + 128)[lane] = hi;
    reinterpret_cast<uint2*>(d_Alo + rb + 128)[lane] = lo;
}

// ---------------- [8] mma.sync GEMM + fused p/q epilogue ---------------------
// BM=64, BN=256, K chunks of 64. 256 thr = 8 warps (4 M-stripes x 2 N-halves).
// 2 CTAs/SM for load/MMA overlap. ldmatrix fragment loads, 144B row pitch.
// bf16 3-term split: Ahi*Bhi + Ahi*Blo + Alo*Bhi.
#define SM_BIAS 0
#define SM_W2L  1024
#define SM_W2R  2048
#define SM_PQ   3072
#define SM_AHI  4096
#define SM_ALO  13312
#define SM_BHI  22528
#define SM_BLO  59392
#define SM_TOT  96256

__device__ __forceinline__ uint32_t smem_u32(const void* p) {
    uint32_t a;
    asm("{ .reg .u64 t; cvta.to.shared.u64 t, %1; cvt.u32.u64 %0, t; }" : "=r"(a) : "l"(p));
    return a;
}
__device__ __forceinline__ void ldsm4(uint32_t& r0, uint32_t& r1, uint32_t& r2,
                                      uint32_t& r3, uint32_t addr) {
    asm volatile("ldmatrix.sync.aligned.m8n8.x4.shared.b16 {%0,%1,%2,%3}, [%4];"
                 : "=r"(r0), "=r"(r1), "=r"(r2), "=r"(r3) : "r"(addr));
}
__device__ __forceinline__ void mma16816(float* c, uint32_t a0, uint32_t a1,
                                         uint32_t a2, uint32_t a3,
                                         uint32_t b0, uint32_t b1) {
    asm volatile(
        "mma.sync.aligned.m16n8k16.row.col.f32.bf16.bf16.f32 "
        "{%0,%1,%2,%3},{%4,%5,%6,%7},{%8,%9},{%0,%1,%2,%3};"
        : "+f"(c[0]), "+f"(c[1]), "+f"(c[2]), "+f"(c[3])
        : "r"(a0), "r"(a1), "r"(a2), "r"(a3), "r"(b0), "r"(b1));
}

__global__ void __launch_bounds__(256, 2)
k_gemm(const float* __restrict__ b1, const float* __restrict__ W2l,
       const float* __restrict__ W2r) {
    extern __shared__ char smem[];
    uint32_t sb = smem_u32(smem);
    int t = threadIdx.x;
    int wid = t >> 5;
    int lane = t & 31;
    int g = lane >> 2;
    int tq = lane & 3;
    int wm = wid & 3;
    int wn = wid >> 2;
    int rowbase = blockIdx.x * 64;

    *reinterpret_cast<float*>(smem + SM_BIAS + t * 4) = b1[t];
    *reinterpret_cast<float*>(smem + SM_W2L + t * 4) = W2l[t];
    *reinterpret_cast<float*>(smem + SM_W2R + t * 4) = W2r[t];

    float acc[64];
#pragma unroll
    for (int i = 0; i < 64; i++) acc[i] = 0.f;

    int arow = wm * 16 + (lane & 15);
    uint32_t a_off = (uint32_t)(arow * 144 + ((lane >> 4) & 1) * 16);
    int bro = (lane >> 4) & 1;
    uint32_t b_off = (uint32_t)(((lane & 7) + bro * 8) * 144 + ((lane >> 3) & 1) * 16);

    for (int ch = 0; ch < 4; ch++) {
        int kbase = ch * 64;
        __syncthreads();
#pragma unroll
        for (int i = 0; i < 2; i++) {
            int v = t + i * 256;
            int row = v >> 3, kg = v & 7;
            int gr = rowbase + row;
            uint4 z = make_uint4(0, 0, 0, 0);
            uint4 a = (gr < NN)
                ? *reinterpret_cast<const uint4*>(d_Ahi + (size_t)gr * KTOT + kbase + kg * 8) : z;
            *reinterpret_cast<uint4*>(smem + SM_AHI + row * 144 + kg * 16) = a;
            uint4 b = (gr < NN)
                ? *reinterpret_cast<const uint4*>(d_Alo + (size_t)gr * KTOT + kbase + kg * 8) : z;
            *reinterpret_cast<uint4*>(smem + SM_ALO + row * 144 + kg * 16) = b;
        }
#pragma unroll
        for (int i = 0; i < 8; i++) {
            int v = t + i * 256;
            int row = v >> 3, kg = v & 7;
            uint4 a = *reinterpret_cast<const uint4*>(d_Whi + (size_t)row * KTOT + kbase + kg * 8);
            *reinterpret_cast<uint4*>(smem + SM_BHI + row * 144 + kg * 16) = a;
            uint4 b = *reinterpret_cast<const uint4*>(d_Wlo + (size_t)row * KTOT + kbase + kg * 8);
            *reinterpret_cast<uint4*>(smem + SM_BLO + row * 144 + kg * 16) = b;
        }
        __syncthreads();

#pragma unroll
        for (int ks = 0; ks < 4; ks++) {
            uint32_t ksb = (uint32_t)(ks * 32);
            uint32_t ah0, ah1, ah2, ah3, al0, al1, al2, al3;
            ldsm4(ah0, ah1, ah2, ah3, sb + SM_AHI + a_off + ksb);
            ldsm4(al0, al1, al2, al3, sb + SM_ALO + a_off + ksb);
#pragma unroll
            for (int jp = 0; jp < 8; jp++) {
                uint32_t brow = (uint32_t)((wn * 128 + jp * 16) * 144);
                uint32_t bh0, bh1, bh2, bh3, bl0, bl1, bl2, bl3;
                ldsm4(bh0, bh1, bh2, bh3, sb + SM_BHI + brow + b_off + ksb);
                ldsm4(bl0, bl1, bl2, bl3, sb + SM_BLO + brow + b_off + ksb);
                float* c0 = acc + jp * 8;
                float* c1 = acc + jp * 8 + 4;
                mma16816(c0, ah0, ah1, ah2, ah3, bh0, bh1);
                mma16816(c0, ah0, ah1, ah2, ah3, bl0, bl1);
                mma16816(c0, al0, al1, al2, al3, bh0, bh1);
                mma16816(c1, ah0, ah1, ah2, ah3, bh2, bh3);
                mma16816(c1, ah0, ah1, ah2, ah3, bl2, bl3);
                mma16816(c1, al0, al1, al2, al3, bh2, bh3);
            }
        }
    }
    __syncthreads();

    const float* s_bias = reinterpret_cast<const float*>(smem + SM_BIAS);
    const float* s_w2l = reinterpret_cast<const float*>(smem + SM_W2L);
    const float* s_w2r = reinterpret_cast<const float*>(smem + SM_W2R);
    float p1 = 0.f, q1 = 0.f, p2 = 0.f, q2 = 0.f;
#pragma unroll
    for (int j = 0; j < 16; j++) {
        int c0 = wn * 128 + j * 8 + 2 * tq;
        float v00 = acc[j * 4 + 0] + s_bias[c0];
        float v01 = acc[j * 4 + 1] + s_bias[c0 + 1];
        float v10 = acc[j * 4 + 2] + s_bias[c0];
        float v11 = acc[j * 4 + 3] + s_bias[c0 + 1];
        v00 = v00 > 0.f ? v00 : 0.f;
        v01 = v01 > 0.f ? v01 : 0.f;
        v10 = v10 > 0.f ? v10 : 0.f;
        v11 = v11 > 0.f ? v11 : 0.f;
        p1 = fmaf(v00, s_w2l[c0], fmaf(v01, s_w2l[c0 + 1], p1));
        q1 = fmaf(v00, s_w2r[c0], fmaf(v01, s_w2r[c0 + 1], q1));
        p2 = fmaf(v10, s_w2l[c0], fmaf(v11, s_w2l[c0 + 1], p2));
        q2 = fmaf(v10, s_w2r[c0], fmaf(v11, s_w2r[c0 + 1], q2));
    }
#pragma unroll
    for (int off = 1; off < 4; off <<= 1) {
        p1 += __shfl_xor_sync(0xffffffffu, p1, off);
        q1 += __shfl_xor_sync(0xffffffffu, q1, off);
        p2 += __shfl_xor_sync(0xffffffffu, p2, off);
        q2 += __shfl_xor_sync(0xffffffffu, q2, off);
    }
    float* pbuf = reinterpret_cast<float*>(smem + SM_PQ);
    float* qbuf = reinterpret_cast<float*>(smem + SM_PQ + 512);
    if (tq == 0) {
        int r1 = wm * 16 + g;
        pbuf[wn * 64 + r1] = p1;
        qbuf[wn * 64 + r1] = q1;
        pbuf[wn * 64 + r1 + 8] = p2;
        qbuf[wn * 64 + r1 + 8] = q2;
    }
    __syncthreads();
    if (t < 64) {
        int gr = rowbase + t;
        if (gr < NN) {
            d_p[gr] = pbuf[t] + pbuf[64 + t];
            d_q[gr] = qbuf[t] + qbuf[64 + t];
        }
    }
}

// ---------------- [9] out = mean_agg(p) + b2 + q -----------------------------
__global__ void k_out(const float* __restrict__ b2, float* __restrict__ out) {
    int warp = threadIdx.x >> 5;
    int lane = threadIdx.x & 31;
    int n = blockIdx.x * 8 + warp;
    if (n >= NN) return;

    int s = d_rowptr[n], e = d_rowptr[n + 1];
    float acc = 0.f;
    for (int j = s + lane; j < e; j += 32) acc += d_p[d_csrc[j]];
#pragma unroll
    for (int off = 16; off > 0; off >>= 1)
        acc += __shfl_down_sync(0xffffffffu, acc, off);
    if (lane == 0) {
        int deg = e - s;
        out[n] = acc / (float)max(deg, 1) + b2[0] + d_q[n];
    }
}

// ---------------- launch -----------------------------------------------------
extern "C" void kernel_launch(void* const* d_in, const int* in_sizes, int n_in,
                              void* d_out, int out_size) {
    const float* x    = (const float*)d_in[0];
    const void*  ei   = d_in[1];
    const float* W1l  = (const float*)d_in[2];
    const float* b1   = (const float*)d_in[3];
    const float* W1r  = (const float*)d_in[4];
    const float* W2l  = (const float*)d_in[5];
    const float* b2   = (const float*)d_in[6];
    const float* W2r  = (const float*)d_in[7];
    float* out = (float*)d_out;

    static int attr_set = 0;
    if (!attr_set) {
        cudaFuncSetAttribute(k_gemm, cudaFuncAttributeMaxDynamicSharedMemorySize, SM_TOT);
        attr_set = 1;
    }

    const int nb_scan = (NN + 1023) / 1024;   // 49

    k_init<<<(HF * KTOT + 255) / 256, 256>>>((const int*)ei, W1l, W1r);
    k_count<<<(NE + 255) / 256, 256>>>(ei);
    k_scan1<<<nb_scan, 256>>>();
    k_scan2<<<1, 32>>>(nb_scan);
    k_scan3<<<(NN + 1023) / 1024, 1024>>>();
    k_fill<<<(NE + 255) / 256, 256>>>(ei);
    k_agg1<<<(NN + 7) / 8, 256>>>(x);
    k_gemm<<<(NN + 63) / 64, 256, SM_TOT>>>(b1, W2l, W2r);
    k_out<<<(NN + 7) / 8, 256>>>(b2, out);
}

// round 11
// speedup vs baseline: 1.5552x; 1.0420x over previous
#include <cuda_runtime.h>
#include <cuda_bf16.h>
#include <cstdint>

#define NN   50000
#define INF  128
#define HF   256
#define NE   800000
#define KTOT 256

// ---------------- scratch (static device globals; no allocation) -------------
__device__ int   d_is64;
__device__ int   d_deg[NN];
__device__ int   d_rowptr[NN + 1];
__device__ int   d_cursor[NN];
__device__ int   d_csrc[NE];
__device__ __align__(16) __nv_bfloat16 d_Ahi[NN * KTOT];  // [agg1 | x] hi
__device__ __align__(16) __nv_bfloat16 d_Alo[NN * KTOT];  // [agg1 | x] lo
__device__ __align__(16) __nv_bfloat16 d_Whi[HF * KTOT];  // Wcat hi (n-major, k contig)
__device__ __align__(16) __nv_bfloat16 d_Wlo[HF * KTOT];  // Wcat lo
__device__ float d_p[NN];
__device__ float d_q[NN];
__device__ int   d_bsum[64];
__device__ int   d_boff[64];

__device__ __forceinline__ int edge_at(const void* ei, long long idx) {
    if (d_is64) return (int)((const long long*)ei)[idx];
    return ((const int*)ei)[idx];
}

// ---------------- [1] init: zero deg + dtype detect + weight prep ------------
__global__ void k_init(const int* __restrict__ ei32,
                       const float* __restrict__ W1l, const float* __restrict__ W1r) {
    int t = blockIdx.x * blockDim.x + threadIdx.x;   // 65536 threads
    if (t == 0) {
        int all0 = 1;
        for (int i = 0; i < 32; i++)
            if (ei32[2 * i + 1] != 0) { all0 = 0; break; }
        d_is64 = all0;
    }
    if (t < NN) d_deg[t] = 0;
    if (t < HF * KTOT) {
        int n = t >> 8, k = t & 255;
        float w = (k < 128) ? W1l[n * 128 + k] : W1r[n * 128 + (k - 128)];
        __nv_bfloat16 h = __float2bfloat16(w);
        __nv_bfloat16 l = __float2bfloat16(w - __bfloat162float(h));
        d_Whi[t] = h;
        d_Wlo[t] = l;
    }
}

// ---------------- [2] count degrees ------------------------------------------
__global__ void k_count(const void* __restrict__ ei) {
    int e = blockIdx.x * blockDim.x + threadIdx.x;
    if (e < NE) {
        int dst = edge_at(ei, (long long)NE + e);
        if ((unsigned)dst < NN) atomicAdd(&d_deg[dst], 1);
    }
}

// ---------------- [3-5] grid-wide exclusive scan -----------------------------
__global__ void k_scan1() {
    __shared__ int sh[256];
    int t = threadIdx.x;
    int base = blockIdx.x * 1024 + t * 4;
    int v[4];
#pragma unroll
    for (int i = 0; i < 4; i++) {
        int idx = base + i;
        v[i] = (idx < NN) ? d_deg[idx] : 0;
    }
    int s = v[0] + v[1] + v[2] + v[3];
    sh[t] = s;
    __syncthreads();
    for (int off = 1; off < 256; off <<= 1) {
        int x_ = (t >= off) ? sh[t - off] : 0;
        __syncthreads();
        sh[t] += x_;
        __syncthreads();
    }
    int run = sh[t] - s;
#pragma unroll
    for (int i = 0; i < 4; i++) {
        int idx = base + i;
        if (idx < NN) d_rowptr[idx] = run;
        run += v[i];
    }
    if (t == 255) d_bsum[blockIdx.x] = sh[255];
}
// parallel scan of block sums (nb <= 64): two warps + cross-warp fixup
__global__ void k_scan2(int nb) {
    int t = threadIdx.x;          // 64 threads
    int lane = t & 31, w = t >> 5;
    __shared__ int w0tot;
    int v = (t < nb) ? d_bsum[t] : 0;
    int inc = v;
#pragma unroll
    for (int off = 1; off < 32; off <<= 1) {
        int u = __shfl_up_sync(0xffffffffu, inc, off);
        if (lane >= off) inc += u;
    }
    if (t == 31) w0tot = inc;
    __syncthreads();
    int excl = inc - v + (w ? w0tot : 0);
    if (t < nb) d_boff[t] = excl;
}
__global__ void k_scan3() {
    int i = blockIdx.x * blockDim.x + threadIdx.x;
    if (i < NN) {
        int r = d_rowptr[i] + d_boff[i >> 10];
        d_rowptr[i] = r;
        d_cursor[i] = r;
    }
    if (i == 0) d_rowptr[NN] = NE;
}

// ---------------- [6] fill CSR -----------------------------------------------
__global__ void k_fill(const void* __restrict__ ei) {
    int e = blockIdx.x * blockDim.x + threadIdx.x;
    if (e < NE) {
        int dst = edge_at(ei, (long long)NE + e);
        int src = edge_at(ei, e);
        if ((unsigned)dst < NN && (unsigned)src < NN) {
            int pos = atomicAdd(&d_cursor[dst], 1);
            if ((unsigned)pos < NE) d_csrc[pos] = src;
        }
    }
}

// ---------------- bf16 hi/lo split helper ------------------------------------
__device__ __forceinline__ void cvt4(float4 v, uint2& hi, uint2& lo) {
    __nv_bfloat16 h0 = __float2bfloat16(v.x), h1 = __float2bfloat16(v.y),
                  h2 = __float2bfloat16(v.z), h3 = __float2bfloat16(v.w);
    __nv_bfloat16 l0 = __float2bfloat16(v.x - __bfloat162float(h0));
    __nv_bfloat16 l1 = __float2bfloat16(v.y - __bfloat162float(h1));
    __nv_bfloat16 l2 = __float2bfloat16(v.z - __bfloat162float(h2));
    __nv_bfloat16 l3 = __float2bfloat16(v.w - __bfloat162float(h3));
    hi.x = (uint32_t)__bfloat16_as_ushort(h0) | ((uint32_t)__bfloat16_as_ushort(h1) << 16);
    hi.y = (uint32_t)__bfloat16_as_ushort(h2) | ((uint32_t)__bfloat16_as_ushort(h3) << 16);
    lo.x = (uint32_t)__bfloat16_as_ushort(l0) | ((uint32_t)__bfloat16_as_ushort(l1) << 16);
    lo.y = (uint32_t)__bfloat16_as_ushort(l2) | ((uint32_t)__bfloat16_as_ushort(l3) << 16);
}

// ---------------- [7] aggregation 1 + pack A=[agg1|x] bf16 hi/lo -------------
__global__ void k_agg1(const float* __restrict__ x) {
    int warp = threadIdx.x >> 5;
    int lane = threadIdx.x & 31;
    int n = blockIdx.x * 8 + warp;
    if (n >= NN) return;

    int s = d_rowptr[n], e = d_rowptr[n + 1];
    float4 acc = make_float4(0.f, 0.f, 0.f, 0.f);
    for (int j = s; j < e; j++) {
        int src = d_csrc[j];
        float4 v = reinterpret_cast<const float4*>(x + (size_t)src * INF)[lane];
        acc.x += v.x; acc.y += v.y; acc.z += v.z; acc.w += v.w;
    }
    int deg = e - s;
    float inv = 1.f / (float)max(deg, 1);
    acc.x *= inv; acc.y *= inv; acc.z *= inv; acc.w *= inv;

    uint2 hi, lo;
    cvt4(acc, hi, lo);
    size_t rb = (size_t)n * KTOT;
    reinterpret_cast<uint2*>(d_Ahi + rb)[lane] = hi;
    reinterpret_cast<uint2*>(d_Alo + rb)[lane] = lo;
    float4 xv = reinterpret_cast<const float4*>(x + (size_t)n * INF)[lane];
    cvt4(xv, hi, lo);
    reinterpret_cast<uint2*>(d_Ahi + rb + 128)[lane] = hi;
    reinterpret_cast<uint2*>(d_Alo + rb + 128)[lane] = lo;
}

// ---------------- [8] cp.async double-buffered GEMM + fused p/q epilogue -----
// BM=128, BN=256, K chunks of 64. 512 thr = 16 warps (8 M x 2 N). 1 CTA/SM.
// 2-stage cp.async pipeline hides chunk loads under MMA of previous chunk.
// bf16 3-term split: Ahi*Bhi + Ahi*Blo + Alo*Bhi. 144B row pitch.
#define SM_BIAS 0
#define SM_W2L  1024
#define SM_W2R  2048
#define SM_PQ   3072          // pbuf[2][128] + qbuf[2][128] = 2048 B
#define SM_DATA 5120
#define OFF_AHI 0             // 128*144 = 18432
#define OFF_ALO 18432
#define OFF_BHI 36864         // 256*144 = 36864
#define OFF_BLO 73728
#define STAGE   110592
#define SM_TOT  (SM_DATA + 2 * STAGE)   // 226304

__device__ __forceinline__ uint32_t smem_u32(const void* p) {
    uint32_t a;
    asm("{ .reg .u64 t; cvta.to.shared.u64 t, %1; cvt.u32.u64 %0, t; }" : "=r"(a) : "l"(p));
    return a;
}
__device__ __forceinline__ void cp16(uint32_t dst, const void* src, int sz) {
    asm volatile("cp.async.cg.shared.global [%0], [%1], 16, %2;"
                 :: "r"(dst), "l"(src), "r"(sz) : "memory");
}
__device__ __forceinline__ void cp_commit() {
    asm volatile("cp.async.commit_group;" ::: "memory");
}
template <int N>
__device__ __forceinline__ void cp_wait() {
    asm volatile("cp.async.wait_group %0;" :: "n"(N) : "memory");
}
__device__ __forceinline__ void ldsm4(uint32_t& r0, uint32_t& r1, uint32_t& r2,
                                      uint32_t& r3, uint32_t addr) {
    asm volatile("ldmatrix.sync.aligned.m8n8.x4.shared.b16 {%0,%1,%2,%3}, [%4];"
                 : "=r"(r0), "=r"(r1), "=r"(r2), "=r"(r3) : "r"(addr));
}
__device__ __forceinline__ void mma16816(float* c, uint32_t a0, uint32_t a1,
                                         uint32_t a2, uint32_t a3,
                                         uint32_t b0, uint32_t b1) {
    asm volatile(
        "mma.sync.aligned.m16n8k16.row.col.f32.bf16.bf16.f32 "
        "{%0,%1,%2,%3},{%4,%5,%6,%7},{%8,%9},{%0,%1,%2,%3};"
        : "+f"(c[0]), "+f"(c[1]), "+f"(c[2]), "+f"(c[3])
        : "r"(a0), "r"(a1), "r"(a2), "r"(a3), "r"(b0), "r"(b1));
}

// issue all cp.async for one K chunk into stage s
__device__ __forceinline__ void issue_chunk(uint32_t sb, int t, int rowbase,
                                            int ch, int s) {
    int kbase = ch * 64;
    uint32_t base = sb + SM_DATA + s * STAGE;
#pragma unroll
    for (int i = 0; i < 2; i++) {              // A: 1024 x 16B each (hi, lo)
        int v = t + i * 512;
        int row = v >> 3, kg = v & 7;
        int gr = rowbase + row;
        int sz = (gr < NN) ? 16 : 0;
        size_t go = (size_t)gr * KTOT + kbase + kg * 8;
        uint32_t so = (uint32_t)(row * 144 + kg * 16);
        cp16(base + OFF_AHI + so, d_Ahi + go, sz);
        cp16(base + OFF_ALO + so, d_Alo + go, sz);
    }
#pragma unroll
    for (int i = 0; i < 4; i++) {              // B: 2048 x 16B each (hi, lo)
        int v = t + i * 512;
        int row = v >> 3, kg = v & 7;
        size_t go = (size_t)row * KTOT + kbase + kg * 8;
        uint32_t so = (uint32_t)(row * 144 + kg * 16);
        cp16(base + OFF_BHI + so, d_Whi + go, 16);
        cp16(base + OFF_BLO + so, d_Wlo + go, 16);
    }
    cp_commit();
}

__global__ void __launch_bounds__(512, 1)
k_gemm(const float* __restrict__ b1, const float* __restrict__ W2l,
       const float* __restrict__ W2r) {
    extern __shared__ char smem[];
    uint32_t sb = smem_u32(smem);
    int t = threadIdx.x;
    int wid = t >> 5;
    int lane = t & 31;
    int g = lane >> 2;
    int tq = lane & 3;
    int wm = wid & 7;         // M stripe (16 rows of 128)
    int wn = wid >> 3;        // N half (128 cols)
    int rowbase = blockIdx.x * 128;

    if (t < 256) {
        *reinterpret_cast<float*>(smem + SM_BIAS + t * 4) = b1[t];
        *reinterpret_cast<float*>(smem + SM_W2L + t * 4) = W2l[t];
        *reinterpret_cast<float*>(smem + SM_W2R + t * 4) = W2r[t];
    }

    float acc[64];
#pragma unroll
    for (int i = 0; i < 64; i++) acc[i] = 0.f;

    // per-thread ldmatrix offsets (within region; + stage base + ks*32 at use)
    int arow = wm * 16 + (lane & 15);
    uint32_t a_off = (uint32_t)(arow * 144 + ((lane >> 4) & 1) * 16);
    int bro = (lane >> 4) & 1;
    uint32_t b_off = (uint32_t)(((lane & 7) + bro * 8) * 144 + ((lane >> 3) & 1) * 16);

    issue_chunk(sb, t, rowbase, 0, 0);

    for (int ch = 0; ch < 4; ch++) {
        if (ch < 3) {
            issue_chunk(sb, t, rowbase, ch + 1, (ch + 1) & 1);
            cp_wait<1>();
        } else {
            cp_wait<0>();
        }
        __syncthreads();

        uint32_t stbase = sb + SM_DATA + (ch & 1) * STAGE;
#pragma unroll
        for (int ks = 0; ks < 4; ks++) {
            uint32_t ksb = (uint32_t)(ks * 32);
            uint32_t ah0, ah1, ah2, ah3, al0, al1, al2, al3;
            ldsm4(ah0, ah1, ah2, ah3, stbase + OFF_AHI + a_off + ksb);
            ldsm4(al0, al1, al2, al3, stbase + OFF_ALO + a_off + ksb);
#pragma unroll
            for (int jp = 0; jp < 8; jp++) {
                uint32_t brow = (uint32_t)((wn * 128 + jp * 16) * 144);
                uint32_t bh0, bh1, bh2, bh3, bl0, bl1, bl2, bl3;
                ldsm4(bh0, bh1, bh2, bh3, stbase + OFF_BHI + brow + b_off + ksb);
                ldsm4(bl0, bl1, bl2, bl3, stbase + OFF_BLO + brow + b_off + ksb);
                float* c0 = acc + jp * 8;
                float* c1 = acc + jp * 8 + 4;
                mma16816(c0, ah0, ah1, ah2, ah3, bh0, bh1);
                mma16816(c0, ah0, ah1, ah2, ah3, bl0, bl1);
                mma16816(c0, al0, al1, al2, al3, bh0, bh1);
                mma16816(c1, ah0, ah1, ah2, ah3, bh2, bh3);
                mma16816(c1, ah0, ah1, ah2, ah3, bl2, bl3);
                mma16816(c1, al0, al1, al2, al3, bh2, bh3);
            }
        }
        __syncthreads();
    }

    // fused epilogue: relu(acc + bias), dot with W2l/W2r
    const float* s_bias = reinterpret_cast<const float*>(smem + SM_BIAS);
    const float* s_w2l = reinterpret_cast<const float*>(smem + SM_W2L);
    const float* s_w2r = reinterpret_cast<const float*>(smem + SM_W2R);
    float p1 = 0.f, q1 = 0.f, p2 = 0.f, q2 = 0.f;
#pragma unroll
    for (int j = 0; j < 16; j++) {
        int c0 = wn * 128 + j * 8 + 2 * tq;
        float v00 = acc[j * 4 + 0] + s_bias[c0];
        float v01 = acc[j * 4 + 1] + s_bias[c0 + 1];
        float v10 = acc[j * 4 + 2] + s_bias[c0];
        float v11 = acc[j * 4 + 3] + s_bias[c0 + 1];
        v00 = v00 > 0.f ? v00 : 0.f;
        v01 = v01 > 0.f ? v01 : 0.f;
        v10 = v10 > 0.f ? v10 : 0.f;
        v11 = v11 > 0.f ? v11 : 0.f;
        p1 = fmaf(v00, s_w2l[c0], fmaf(v01, s_w2l[c0 + 1], p1));
        q1 = fmaf(v00, s_w2r[c0], fmaf(v01, s_w2r[c0 + 1], q1));
        p2 = fmaf(v10, s_w2l[c0], fmaf(v11, s_w2l[c0 + 1], p2));
        q2 = fmaf(v10, s_w2r[c0], fmaf(v11, s_w2r[c0 + 1], q2));
    }
#pragma unroll
    for (int off = 1; off < 4; off <<= 1) {
        p1 += __shfl_xor_sync(0xffffffffu, p1, off);
        q1 += __shfl_xor_sync(0xffffffffu, q1, off);
        p2 += __shfl_xor_sync(0xffffffffu, p2, off);
        q2 += __shfl_xor_sync(0xffffffffu, q2, off);
    }
    float* pbuf = reinterpret_cast<float*>(smem + SM_PQ);           // [2][128]
    float* qbuf = reinterpret_cast<float*>(smem + SM_PQ + 1024);    // [2][128]
    if (tq == 0) {
        int r1 = wm * 16 + g;
        pbuf[wn * 128 + r1] = p1;
        qbuf[wn * 128 + r1] = q1;
        pbuf[wn * 128 + r1 + 8] = p2;
        qbuf[wn * 128 + r1 + 8] = q2;
    }
    __syncthreads();
    if (t < 128) {
        int gr = rowbase + t;
        if (gr < NN) {
            d_p[gr] = pbuf[t] + pbuf[128 + t];
            d_q[gr] = qbuf[t] + qbuf[128 + t];
        }
    }
}

// ---------------- [9] out = mean_agg(p) + b2 + q -----------------------------
__global__ void k_out(const float* __restrict__ b2, float* __restrict__ out) {
    int warp = threadIdx.x >> 5;
    int lane = threadIdx.x & 31;
    int n = blockIdx.x * 8 + warp;
    if (n >= NN) return;

    int s = d_rowptr[n], e = d_rowptr[n + 1];
    float acc = 0.f;
    for (int j = s + lane; j < e; j += 32) acc += d_p[d_csrc[j]];
#pragma unroll
    for (int off = 16; off > 0; off >>= 1)
        acc += __shfl_down_sync(0xffffffffu, acc, off);
    if (lane == 0) {
        int deg = e - s;
        out[n] = acc / (float)max(deg, 1) + b2[0] + d_q[n];
    }
}

// ---------------- launch -----------------------------------------------------
extern "C" void kernel_launch(void* const* d_in, const int* in_sizes, int n_in,
                              void* d_out, int out_size) {
    const float* x    = (const float*)d_in[0];
    const void*  ei   = d_in[1];
    const float* W1l  = (const float*)d_in[2];
    const float* b1   = (const float*)d_in[3];
    const float* W1r  = (const float*)d_in[4];
    const float* W2l  = (const float*)d_in[5];
    const float* b2   = (const float*)d_in[6];
    const float* W2r  = (const float*)d_in[7];
    float* out = (float*)d_out;

    static int attr_set = 0;
    if (!attr_set) {
        cudaFuncSetAttribute(k_gemm, cudaFuncAttributeMaxDynamicSharedMemorySize, SM_TOT);
        attr_set = 1;
    }

    const int nb_scan = (NN + 1023) / 1024;   // 49

    k_init<<<(HF * KTOT + 255) / 256, 256>>>((const int*)ei, W1l, W1r);
    k_count<<<(NE + 255) / 256, 256>>>(ei);
    k_scan1<<<nb_scan, 256>>>();
    k_scan2<<<1, 64>>>(nb_scan);
    k_scan3<<<(NN + 1023) / 1024, 1024>>>();
    k_fill<<<(NE + 255) / 256, 256>>>(ei);
    k_agg1<<<(NN + 7) / 8, 256>>>(x);
    k_gemm<<<(NN + 127) / 128, 512, SM_TOT>>>(b1, W2l, W2r);
    k_out<<<(NN + 7) / 8, 256>>>(b2, out);
}

// round 12
// speedup vs baseline: 1.8201x; 1.1703x over previous
#include <cuda_runtime.h>
#include <cuda_fp16.h>
#include <cstdint>

#define NN   50000
#define INF  128
#define HF   256
#define NE   800000
#define KTOT 256

// ---------------- scratch (static device globals; no allocation) -------------
__device__ int   d_is64;
__device__ int   d_deg[NN];
__device__ int   d_rowptr[NN + 1];
__device__ int   d_cursor[NN];
__device__ int   d_csrc[NE];
__device__ __align__(16) __half d_Ah[NN * KTOT];   // [agg1 | x] fp16 (single)
__device__ __align__(16) __half d_Whi[HF * KTOT];  // Wcat hi (n-major, k contig)
__device__ __align__(16) __half d_Wlo[HF * KTOT];  // Wcat lo
__device__ float d_p[NN];
__device__ float d_q[NN];
__device__ int   d_bsum[64];

__device__ __forceinline__ int edge_at(const void* ei, long long idx) {
    if (d_is64) return (int)((const long long*)ei)[idx];
    return ((const int*)ei)[idx];
}

// ---------------- [1] init: zero deg + dtype detect + weight prep ------------
__global__ void k_init(const int* __restrict__ ei32,
                       const float* __restrict__ W1l, const float* __restrict__ W1r) {
    int t = blockIdx.x * blockDim.x + threadIdx.x;   // 65536 threads
    if (t == 0) {
        int all0 = 1;
        for (int i = 0; i < 32; i++)
            if (ei32[2 * i + 1] != 0) { all0 = 0; break; }
        d_is64 = all0;
    }
    if (t < NN) d_deg[t] = 0;
    if (t < HF * KTOT) {
        int n = t >> 8, k = t & 255;
        float w = (k < 128) ? W1l[n * 128 + k] : W1r[n * 128 + (k - 128)];
        __half h = __float2half_rn(w);
        __half l = __float2half_rn(w - __half2float(h));
        d_Whi[t] = h;
        d_Wlo[t] = l;
    }
}

// ---------------- [2] count degrees ------------------------------------------
__global__ void k_count(const void* __restrict__ ei) {
    int e = blockIdx.x * blockDim.x + threadIdx.x;
    if (e < NE) {
        int dst = edge_at(ei, (long long)NE + e);
        if ((unsigned)dst < NN) atomicAdd(&d_deg[dst], 1);
    }
}

// ---------------- [3-4] grid-wide exclusive scan -----------------------------
__global__ void k_scan1() {
    __shared__ int sh[256];
    int t = threadIdx.x;
    int base = blockIdx.x * 1024 + t * 4;
    int v[4];
#pragma unroll
    for (int i = 0; i < 4; i++) {
        int idx = base + i;
        v[i] = (idx < NN) ? d_deg[idx] : 0;
    }
    int s = v[0] + v[1] + v[2] + v[3];
    sh[t] = s;
    __syncthreads();
    for (int off = 1; off < 256; off <<= 1) {
        int x_ = (t >= off) ? sh[t - off] : 0;
        __syncthreads();
        sh[t] += x_;
        __syncthreads();
    }
    int run = sh[t] - s;
#pragma unroll
    for (int i = 0; i < 4; i++) {
        int idx = base + i;
        if (idx < NN) d_rowptr[idx] = run;
        run += v[i];
    }
    if (t == 255) d_bsum[blockIdx.x] = sh[255];
}
// fixup: each block adds Σ bsum[i < blockIdx] (reduction, not scan)
__global__ void __launch_bounds__(1024) k_scan3() {
    __shared__ int boff_sh;
    int lane = threadIdx.x & 31;
    if (threadIdx.x < 32) {
        int s = 0;
        for (int i = lane; i < blockIdx.x; i += 32) s += d_bsum[i];
#pragma unroll
        for (int off = 16; off > 0; off >>= 1)
            s += __shfl_down_sync(0xffffffffu, s, off);
        if (lane == 0) boff_sh = s;
    }
    __syncthreads();
    int i = blockIdx.x * 1024 + threadIdx.x;
    if (i < NN) {
        int r = d_rowptr[i] + boff_sh;
        d_rowptr[i] = r;
        d_cursor[i] = r;
    }
    if (i == 0) d_rowptr[NN] = NE;
}

// ---------------- [5] fill CSR -----------------------------------------------
__global__ void k_fill(const void* __restrict__ ei) {
    int e = blockIdx.x * blockDim.x + threadIdx.x;
    if (e < NE) {
        int dst = edge_at(ei, (long long)NE + e);
        int src = edge_at(ei, e);
        if ((unsigned)dst < NN && (unsigned)src < NN) {
            int pos = atomicAdd(&d_cursor[dst], 1);
            if ((unsigned)pos < NE) d_csrc[pos] = src;
        }
    }
}

// ---------------- fp16 pack helper -------------------------------------------
__device__ __forceinline__ uint2 cvt4h(float4 v) {
    __half2 a = make_half2(__float2half_rn(v.x), __float2half_rn(v.y));
    __half2 b = make_half2(__float2half_rn(v.z), __float2half_rn(v.w));
    uint2 r;
    r.x = *reinterpret_cast<uint32_t*>(&a);
    r.y = *reinterpret_cast<uint32_t*>(&b);
    return r;
}

// ---------------- [6] aggregation 1 + pack A=[agg1|x] fp16 -------------------
__global__ void k_agg1(const float* __restrict__ x) {
    int warp = threadIdx.x >> 5;
    int lane = threadIdx.x & 31;
    int n = blockIdx.x * 8 + warp;
    if (n >= NN) return;

    int s = d_rowptr[n], e = d_rowptr[n + 1];
    float4 acc = make_float4(0.f, 0.f, 0.f, 0.f);
    for (int j = s; j < e; j++) {
        int src = d_csrc[j];
        float4 v = reinterpret_cast<const float4*>(x + (size_t)src * INF)[lane];
        acc.x += v.x; acc.y += v.y; acc.z += v.z; acc.w += v.w;
    }
    int deg = e - s;
    float inv = 1.f / (float)max(deg, 1);
    acc.x *= inv; acc.y *= inv; acc.z *= inv; acc.w *= inv;

    size_t rb = (size_t)n * KTOT;
    reinterpret_cast<uint2*>(d_Ah + rb)[lane] = cvt4h(acc);
    float4 xv = reinterpret_cast<const float4*>(x + (size_t)n * INF)[lane];
    reinterpret_cast<uint2*>(d_Ah + rb + 128)[lane] = cvt4h(xv);
}

// ---------------- [7] cp.async double-buffered fp16 GEMM + fused epilogue ----
// BM=128, BN=256, K chunks of 64. 512 thr = 16 warps (8 M x 2 N). 1 CTA/SM.
// 2-term fp16 split: Ah*Bhi + Ah*Blo (dropped Al*Bh term ~2^-12 rel).
#define SM_BIAS 0
#define SM_W2L  1024
#define SM_W2R  2048
#define SM_PQ   3072          // pbuf[2][128] + qbuf[2][128] = 2048 B
#define SM_DATA 5120
#define OFF_A   0             // 128*144 = 18432
#define OFF_BHI 18432         // 256*144 = 36864
#define OFF_BLO 55296
#define STAGE   92160
#define SM_TOT  (SM_DATA + 2 * STAGE)   // 189440

__device__ __forceinline__ uint32_t smem_u32(const void* p) {
    uint32_t a;
    asm("{ .reg .u64 t; cvta.to.shared.u64 t, %1; cvt.u32.u64 %0, t; }" : "=r"(a) : "l"(p));
    return a;
}
__device__ __forceinline__ void cp16(uint32_t dst, const void* src, int sz) {
    asm volatile("cp.async.cg.shared.global [%0], [%1], 16, %2;"
                 :: "r"(dst), "l"(src), "r"(sz) : "memory");
}
__device__ __forceinline__ void cp_commit() {
    asm volatile("cp.async.commit_group;" ::: "memory");
}
template <int N>
__device__ __forceinline__ void cp_wait() {
    asm volatile("cp.async.wait_group %0;" :: "n"(N) : "memory");
}
__device__ __forceinline__ void ldsm4(uint32_t& r0, uint32_t& r1, uint32_t& r2,
                                      uint32_t& r3, uint32_t addr) {
    asm volatile("ldmatrix.sync.aligned.m8n8.x4.shared.b16 {%0,%1,%2,%3}, [%4];"
                 : "=r"(r0), "=r"(r1), "=r"(r2), "=r"(r3) : "r"(addr));
}
__device__ __forceinline__ void mma16816(float* c, uint32_t a0, uint32_t a1,
                                         uint32_t a2, uint32_t a3,
                                         uint32_t b0, uint32_t b1) {
    asm volatile(
        "mma.sync.aligned.m16n8k16.row.col.f32.f16.f16.f32 "
        "{%0,%1,%2,%3},{%4,%5,%6,%7},{%8,%9},{%0,%1,%2,%3};"
        : "+f"(c[0]), "+f"(c[1]), "+f"(c[2]), "+f"(c[3])
        : "r"(a0), "r"(a1), "r"(a2), "r"(a3), "r"(b0), "r"(b1));
}

// issue all cp.async for one K chunk into stage s
__device__ __forceinline__ void issue_chunk(uint32_t sb, int t, int rowbase,
                                            int ch, int s) {
    int kbase = ch * 64;
    uint32_t base = sb + SM_DATA + s * STAGE;
#pragma unroll
    for (int i = 0; i < 2; i++) {              // A: 1024 x 16B
        int v = t + i * 512;
        int row = v >> 3, kg = v & 7;
        int gr = rowbase + row;
        int sz = (gr < NN) ? 16 : 0;
        size_t go = (size_t)gr * KTOT + kbase + kg * 8;
        uint32_t so = (uint32_t)(row * 144 + kg * 16);
        cp16(base + OFF_A + so, d_Ah + go, sz);
    }
#pragma unroll
    for (int i = 0; i < 4; i++) {              // B: 2048 x 16B each (hi, lo)
        int v = t + i * 512;
        int row = v >> 3, kg = v & 7;
        size_t go = (size_t)row * KTOT + kbase + kg * 8;
        uint32_t so = (uint32_t)(row * 144 + kg * 16);
        cp16(base + OFF_BHI + so, d_Whi + go, 16);
        cp16(base + OFF_BLO + so, d_Wlo + go, 16);
    }
    cp_commit();
}

__global__ void __launch_bounds__(512, 1)
k_gemm(const float* __restrict__ b1, const float* __restrict__ W2l,
       const float* __restrict__ W2r) {
    extern __shared__ char smem[];
    uint32_t sb = smem_u32(smem);
    int t = threadIdx.x;
    int wid = t >> 5;
    int lane = t & 31;
    int g = lane >> 2;
    int tq = lane & 3;
    int wm = wid & 7;         // M stripe (16 rows of 128)
    int wn = wid >> 3;        // N half (128 cols)
    int rowbase = blockIdx.x * 128;

    if (t < 256) {
        *reinterpret_cast<float*>(smem + SM_BIAS + t * 4) = b1[t];
        *reinterpret_cast<float*>(smem + SM_W2L + t * 4) = W2l[t];
        *reinterpret_cast<float*>(smem + SM_W2R + t * 4) = W2r[t];
    }

    float acc[64];
#pragma unroll
    for (int i = 0; i < 64; i++) acc[i] = 0.f;

    int arow = wm * 16 + (lane & 15);
    uint32_t a_off = (uint32_t)(arow * 144 + ((lane >> 4) & 1) * 16);
    int bro = (lane >> 4) & 1;
    uint32_t b_off = (uint32_t)(((lane & 7) + bro * 8) * 144 + ((lane >> 3) & 1) * 16);

    issue_chunk(sb, t, rowbase, 0, 0);

    for (int ch = 0; ch < 4; ch++) {
        if (ch < 3) {
            issue_chunk(sb, t, rowbase, ch + 1, (ch + 1) & 1);
            cp_wait<1>();
        } else {
            cp_wait<0>();
        }
        __syncthreads();

        uint32_t stbase = sb + SM_DATA + (ch & 1) * STAGE;
#pragma unroll
        for (int ks = 0; ks < 4; ks++) {
            uint32_t ksb = (uint32_t)(ks * 32);
            uint32_t a0, a1, a2, a3;
            ldsm4(a0, a1, a2, a3, stbase + OFF_A + a_off + ksb);
#pragma unroll
            for (int jp = 0; jp < 8; jp++) {
                uint32_t brow = (uint32_t)((wn * 128 + jp * 16) * 144);
                uint32_t bh0, bh1, bh2, bh3, bl0, bl1, bl2, bl3;
                ldsm4(bh0, bh1, bh2, bh3, stbase + OFF_BHI + brow + b_off + ksb);
                ldsm4(bl0, bl1, bl2, bl3, stbase + OFF_BLO + brow + b_off + ksb);
                float* c0 = acc + jp * 8;
                float* c1 = acc + jp * 8 + 4;
                mma16816(c0, a0, a1, a2, a3, bh0, bh1);
                mma16816(c0, a0, a1, a2, a3, bl0, bl1);
                mma16816(c1, a0, a1, a2, a3, bh2, bh3);
                mma16816(c1, a0, a1, a2, a3, bl2, bl3);
            }
        }
        __syncthreads();
    }

    // fused epilogue: relu(acc + bias), dot with W2l/W2r
    const float* s_bias = reinterpret_cast<const float*>(smem + SM_BIAS);
    const float* s_w2l = reinterpret_cast<const float*>(smem + SM_W2L);
    const float* s_w2r = reinterpret_cast<const float*>(smem + SM_W2R);
    float p1 = 0.f, q1 = 0.f, p2 = 0.f, q2 = 0.f;
#pragma unroll
    for (int j = 0; j < 16; j++) {
        int c0 = wn * 128 + j * 8 + 2 * tq;
        float v00 = acc[j * 4 + 0] + s_bias[c0];
        float v01 = acc[j * 4 + 1] + s_bias[c0 + 1];
        float v10 = acc[j * 4 + 2] + s_bias[c0];
        float v11 = acc[j * 4 + 3] + s_bias[c0 + 1];
        v00 = v00 > 0.f ? v00 : 0.f;
        v01 = v01 > 0.f ? v01 : 0.f;
        v10 = v10 > 0.f ? v10 : 0.f;
        v11 = v11 > 0.f ? v11 : 0.f;
        p1 = fmaf(v00, s_w2l[c0], fmaf(v01, s_w2l[c0 + 1], p1));
        q1 = fmaf(v00, s_w2r[c0], fmaf(v01, s_w2r[c0 + 1], q1));
        p2 = fmaf(v10, s_w2l[c0], fmaf(v11, s_w2l[c0 + 1], p2));
        q2 = fmaf(v10, s_w2r[c0], fmaf(v11, s_w2r[c0 + 1], q2));
    }
#pragma unroll
    for (int off = 1; off < 4; off <<= 1) {
        p1 += __shfl_xor_sync(0xffffffffu, p1, off);
        q1 += __shfl_xor_sync(0xffffffffu, q1, off);
        p2 += __shfl_xor_sync(0xffffffffu, p2, off);
        q2 += __shfl_xor_sync(0xffffffffu, q2, off);
    }
    float* pbuf = reinterpret_cast<float*>(smem + SM_PQ);           // [2][128]
    float* qbuf = reinterpret_cast<float*>(smem + SM_PQ + 1024);    // [2][128]
    if (tq == 0) {
        int r1 = wm * 16 + g;
        pbuf[wn * 128 + r1] = p1;
        qbuf[wn * 128 + r1] = q1;
        pbuf[wn * 128 + r1 + 8] = p2;
        qbuf[wn * 128 + r1 + 8] = q2;
    }
    __syncthreads();
    if (t < 128) {
        int gr = rowbase + t;
        if (gr < NN) {
            d_p[gr] = pbuf[t] + pbuf[128 + t];
            d_q[gr] = qbuf[t] + qbuf[128 + t];
        }
    }
}

// ---------------- [8] out = mean_agg(p) + b2 + q -----------------------------
__global__ void k_out(const float* __restrict__ b2, float* __restrict__ out) {
    int warp = threadIdx.x >> 5;
    int lane = threadIdx.x & 31;
    int n = blockIdx.x * 8 + warp;
    if (n >= NN) return;

    int s = d_rowptr[n], e = d_rowptr[n + 1];
    float acc = 0.f;
    for (int j = s + lane; j < e; j += 32) acc += d_p[d_csrc[j]];
#pragma unroll
    for (int off = 16; off > 0; off >>= 1)
        acc += __shfl_down_sync(0xffffffffu, acc, off);
    if (lane == 0) {
        int deg = e - s;
        out[n] = acc / (float)max(deg, 1) + b2[0] + d_q[n];
    }
}

// ---------------- launch -----------------------------------------------------
extern "C" void kernel_launch(void* const* d_in, const int* in_sizes, int n_in,
                              void* d_out, int out_size) {
    const float* x    = (const float*)d_in[0];
    const void*  ei   = d_in[1];
    const float* W1l  = (const float*)d_in[2];
    const float* b1   = (const float*)d_in[3];
    const float* W1r  = (const float*)d_in[4];
    const float* W2l  = (const float*)d_in[5];
    const float* b2   = (const float*)d_in[6];
    const float* W2r  = (const float*)d_in[7];
    float* out = (float*)d_out;

    static int attr_set = 0;
    if (!attr_set) {
        cudaFuncSetAttribute(k_gemm, cudaFuncAttributeMaxDynamicSharedMemorySize, SM_TOT);
        attr_set = 1;
    }

    const int nb_scan = (NN + 1023) / 1024;   // 49

    k_init<<<(HF * KTOT + 255) / 256, 256>>>((const int*)ei, W1l, W1r);
    k_count<<<(NE + 255) / 256, 256>>>(ei);
    k_scan1<<<nb_scan, 256>>>();
    k_scan3<<<nb_scan, 1024>>>();
    k_fill<<<(NE + 255) / 256, 256>>>(ei);
    k_agg1<<<(NN + 7) / 8, 256>>>(x);
    k_gemm<<<(NN + 127) / 128, 512, SM_TOT>>>(b1, W2l, W2r);
    k_out<<<(NN + 7) / 8, 256>>>(b2, out);
}

// round 15
// speedup vs baseline: 2.2162x; 1.2176x over previous
#include <cuda_runtime.h>
#include <cuda_fp16.h>
#include <cstdint>

#define NN   50000
#define INF  128
#define HF   256
#define NE   800000
#define KTOT 256

// ---------------- scratch (static device globals; no allocation) -------------
__device__ int   d_is64;
__device__ int   d_deg[NN];
__device__ int   d_rowptr[NN + 1];
__device__ int   d_cursor[NN];
__device__ int   d_csrc[NE];
__device__ __align__(16) __half d_xh[NN * INF];    // x in fp16
__device__ __align__(16) __half d_Ah[NN * KTOT];   // [agg1 | x] fp16
__device__ __align__(16) __half d_Wh[HF * KTOT];   // Wcat fp16 (n-major, k contig)
__device__ float d_p[NN];
__device__ float d_q[NN];
__device__ int   d_bsum[64];

__device__ __forceinline__ int edge_at(const void* ei, long long idx) {
    if (d_is64) return (int)((const long long*)ei)[idx];
    return ((const int*)ei)[idx];
}

// ---------------- [1] init: zero deg + detect + weight prep + x->fp16 --------
__global__ void k_init(const int* __restrict__ ei32, const float* __restrict__ x,
                       const float* __restrict__ W1l, const float* __restrict__ W1r) {
    int t = blockIdx.x * blockDim.x + threadIdx.x;   // 65536 threads
    if (t == 0) {
        int all0 = 1;
        for (int i = 0; i < 32; i++)
            if (ei32[2 * i + 1] != 0) { all0 = 0; break; }
        d_is64 = all0;
    }
    if (t < NN) d_deg[t] = 0;
    if (t < HF * KTOT) {
        int n = t >> 8, k = t & 255;
        float w = (k < 128) ? W1l[n * 128 + k] : W1r[n * 128 + (k - 128)];
        d_Wh[t] = __float2half_rn(w);
    }
    // x -> fp16 (grid-stride over 1.6M float4 groups)
    const int NG = NN * INF / 4;
    for (int i = t; i < NG; i += 65536) {
        float4 v = reinterpret_cast<const float4*>(x)[i];
        __half2 a = make_half2(__float2half_rn(v.x), __float2half_rn(v.y));
        __half2 b = make_half2(__float2half_rn(v.z), __float2half_rn(v.w));
        uint2 r;
        r.x = *reinterpret_cast<uint32_t*>(&a);
        r.y = *reinterpret_cast<uint32_t*>(&b);
        reinterpret_cast<uint2*>(d_xh)[i] = r;
    }
}

// ---------------- [2] count degrees ------------------------------------------
__global__ void k_count(const void* __restrict__ ei) {
    int e = blockIdx.x * blockDim.x + threadIdx.x;
    if (e < NE) {
        int dst = edge_at(ei, (long long)NE + e);
        if ((unsigned)dst < NN) atomicAdd(&d_deg[dst], 1);
    }
}

// ---------------- [3-4] grid-wide exclusive scan -----------------------------
__global__ void k_scan1() {
    __shared__ int sh[256];
    int t = threadIdx.x;
    int base = blockIdx.x * 1024 + t * 4;
    int v[4];
#pragma unroll
    for (int i = 0; i < 4; i++) {
        int idx = base + i;
        v[i] = (idx < NN) ? d_deg[idx] : 0;
    }
    int s = v[0] + v[1] + v[2] + v[3];
    sh[t] = s;
    __syncthreads();
    for (int off = 1; off < 256; off <<= 1) {
        int x_ = (t >= off) ? sh[t - off] : 0;
        __syncthreads();
        sh[t] += x_;
        __syncthreads();
    }
    int run = sh[t] - s;
#pragma unroll
    for (int i = 0; i < 4; i++) {
        int idx = base + i;
        if (idx < NN) d_rowptr[idx] = run;
        run += v[i];
    }
    if (t == 255) d_bsum[blockIdx.x] = sh[255];
}
// fixup: each block adds sum of bsum[i < blockIdx]
__global__ void __launch_bounds__(1024) k_scan3() {
    __shared__ int boff_sh;
    int lane = threadIdx.x & 31;
    if (threadIdx.x < 32) {
        int s = 0;
        for (int i = lane; i < blockIdx.x; i += 32) s += d_bsum[i];
#pragma unroll
        for (int off = 16; off > 0; off >>= 1)
            s += __shfl_down_sync(0xffffffffu, s, off);
        if (lane == 0) boff_sh = s;
    }
    __syncthreads();
    int i = blockIdx.x * 1024 + threadIdx.x;
    if (i < NN) {
        int r = d_rowptr[i] + boff_sh;
        d_rowptr[i] = r;
        d_cursor[i] = r;
    }
    if (i == 0) d_rowptr[NN] = NE;
}

// ---------------- [5] fill CSR -----------------------------------------------
__global__ void k_fill(const void* __restrict__ ei) {
    int e = blockIdx.x * blockDim.x + threadIdx.x;
    if (e < NE) {
        int dst = edge_at(ei, (long long)NE + e);
        int src = edge_at(ei, e);
        if ((unsigned)dst < NN && (unsigned)src < NN) {
            int pos = atomicAdd(&d_cursor[dst], 1);
            if ((unsigned)pos < NE) d_csrc[pos] = src;
        }
    }
}

// ---------------- [6] aggregation 1 (fp16 gather) + pack A=[agg1|x] ----------
__global__ void k_agg1() {
    int warp = threadIdx.x >> 5;
    int lane = threadIdx.x & 31;
    int n = blockIdx.x * 8 + warp;
    if (n >= NN) return;

    int s = d_rowptr[n], e = d_rowptr[n + 1];
    float4 acc = make_float4(0.f, 0.f, 0.f, 0.f);
    for (int j = s; j < e; j++) {
        int src = d_csrc[j];
        uint2 v = reinterpret_cast<const uint2*>(d_xh + (size_t)src * INF)[lane];
        float2 f0 = __half22float2(*reinterpret_cast<__half2*>(&v.x));
        float2 f1 = __half22float2(*reinterpret_cast<__half2*>(&v.y));
        acc.x += f0.x; acc.y += f0.y; acc.z += f1.x; acc.w += f1.y;
    }
    int deg = e - s;
    float inv = 1.f / (float)max(deg, 1);
    __half2 a = make_half2(__float2half_rn(acc.x * inv), __float2half_rn(acc.y * inv));
    __half2 b = make_half2(__float2half_rn(acc.z * inv), __float2half_rn(acc.w * inv));
    uint2 m;
    m.x = *reinterpret_cast<uint32_t*>(&a);
    m.y = *reinterpret_cast<uint32_t*>(&b);

    size_t rb = (size_t)n * KTOT;
    reinterpret_cast<uint2*>(d_Ah + rb)[lane] = m;
    reinterpret_cast<uint2*>(d_Ah + rb + 128)[lane] =
        reinterpret_cast<const uint2*>(d_xh + (size_t)n * INF)[lane];
}

// ---------------- [7] cp.async double-buffered fp16 GEMM + fused epilogue ----
// BM=128, BN=256, K chunks of 64. 512 thr = 16 warps (8 M x 2 N).
// Single-term fp16: A*W (A err 2^-12, W err 2^-12 -> ~3.4e-4 total).
#define SM_BIAS 0
#define SM_W2L  1024
#define SM_W2R  2048
#define SM_PQ   3072          // pbuf[2][128] + qbuf[2][128] = 2048 B
#define SM_DATA 5120
#define OFF_A   0             // 128*144 = 18432
#define OFF_B   18432         // 256*144 = 36864
#define STAGE   55296
#define SM_TOT  (SM_DATA + 2 * STAGE)   // 115712

__device__ __forceinline__ uint32_t smem_u32(const void* p) {
    uint32_t a;
    asm("{ .reg .u64 t; cvta.to.shared.u64 t, %1; cvt.u32.u64 %0, t; }" : "=r"(a) : "l"(p));
    return a;
}
__device__ __forceinline__ void cp16(uint32_t dst, const void* src, int sz) {
    asm volatile("cp.async.cg.shared.global [%0], [%1], 16, %2;"
                 :: "r"(dst), "l"(src), "r"(sz) : "memory");
}
__device__ __forceinline__ void cp_commit() {
    asm volatile("cp.async.commit_group;" ::: "memory");
}
template <int N>
__device__ __forceinline__ void cp_wait() {
    asm volatile("cp.async.wait_group %0;" :: "n"(N) : "memory");
}
__device__ __forceinline__ void ldsm4(uint32_t& r0, uint32_t& r1, uint32_t& r2,
                                      uint32_t& r3, uint32_t addr) {
    asm volatile("ldmatrix.sync.aligned.m8n8.x4.shared.b16 {%0,%1,%2,%3}, [%4];"
                 : "=r"(r0), "=r"(r1), "=r"(r2), "=r"(r3) : "r"(addr));
}
__device__ __forceinline__ void mma16816(float* c, uint32_t a0, uint32_t a1,
                                         uint32_t a2, uint32_t a3,
                                         uint32_t b0, uint32_t b1) {
    asm volatile(
        "mma.sync.aligned.m16n8k16.row.col.f32.f16.f16.f32 "
        "{%0,%1,%2,%3},{%4,%5,%6,%7},{%8,%9},{%0,%1,%2,%3};"
        : "+f"(c[0]), "+f"(c[1]), "+f"(c[2]), "+f"(c[3])
        : "r"(a0), "r"(a1), "r"(a2), "r"(a3), "r"(b0), "r"(b1));
}

__device__ __forceinline__ void issue_chunk(uint32_t sb, int t, int rowbase,
                                            int ch, int s) {
    int kbase = ch * 64;
    uint32_t base = sb + SM_DATA + s * STAGE;
#pragma unroll
    for (int i = 0; i < 2; i++) {              // A: 1024 x 16B
        int v = t + i * 512;
        int row = v >> 3, kg = v & 7;
        int gr = rowbase + row;
        int sz = (gr < NN) ? 16 : 0;
        size_t go = (size_t)gr * KTOT + kbase + kg * 8;
        uint32_t so = (uint32_t)(row * 144 + kg * 16);
        cp16(base + OFF_A + so, d_Ah + go, sz);
    }
#pragma unroll
    for (int i = 0; i < 4; i++) {              // B: 2048 x 16B
        int v = t + i * 512;
        int row = v >> 3, kg = v & 7;
        size_t go = (size_t)row * KTOT + kbase + kg * 8;
        uint32_t so = (uint32_t)(row * 144 + kg * 16);
        cp16(base + OFF_B + so, d_Wh + go, 16);
    }
    cp_commit();
}

__global__ void __launch_bounds__(512, 1)
k_gemm(const float* __restrict__ b1, const float* __restrict__ W2l,
       const float* __restrict__ W2r) {
    extern __shared__ char smem[];
    uint32_t sb = smem_u32(smem);
    int t = threadIdx.x;
    int wid = t >> 5;
    int lane = t & 31;
    int g = lane >> 2;
    int tq = lane & 3;
    int wm = wid & 7;         // M stripe (16 rows of 128)
    int wn = wid >> 3;        // N half (128 cols)
    int rowbase = blockIdx.x * 128;

    if (t < 256) {
        *reinterpret_cast<float*>(smem + SM_BIAS + t * 4) = b1[t];
        *reinterpret_cast<float*>(smem + SM_W2L + t * 4) = W2l[t];
        *reinterpret_cast<float*>(smem + SM_W2R + t * 4) = W2r[t];
    }

    float acc[64];
#pragma unroll
    for (int i = 0; i < 64; i++) acc[i] = 0.f;

    int arow = wm * 16 + (lane & 15);
    uint32_t a_off = (uint32_t)(arow * 144 + ((lane >> 4) & 1) * 16);
    int bro = (lane >> 4) & 1;
    uint32_t b_off = (uint32_t)(((lane & 7) + bro * 8) * 144 + ((lane >> 3) & 1) * 16);

    issue_chunk(sb, t, rowbase, 0, 0);

    for (int ch = 0; ch < 4; ch++) {
        if (ch < 3) {
            issue_chunk(sb, t, rowbase, ch + 1, (ch + 1) & 1);
            cp_wait<1>();
        } else {
            cp_wait<0>();
        }
        __syncthreads();

        uint32_t stbase = sb + SM_DATA + (ch & 1) * STAGE;
#pragma unroll
        for (int ks = 0; ks < 4; ks++) {
            uint32_t ksb = (uint32_t)(ks * 32);
            uint32_t a0, a1, a2, a3;
            ldsm4(a0, a1, a2, a3, stbase + OFF_A + a_off + ksb);
#pragma unroll
            for (int jp = 0; jp < 8; jp++) {
                uint32_t brow = (uint32_t)((wn * 128 + jp * 16) * 144);
                uint32_t b0, b1v, b2v, b3;
                ldsm4(b0, b1v, b2v, b3, stbase + OFF_B + brow + b_off + ksb);
                mma16816(acc + jp * 8, a0, a1, a2, a3, b0, b1v);
                mma16816(acc + jp * 8 + 4, a0, a1, a2, a3, b2v, b3);
            }
        }
        __syncthreads();
    }

    // fused epilogue: relu(acc + bias), dot with W2l/W2r
    const float* s_bias = reinterpret_cast<const float*>(smem + SM_BIAS);
    const float* s_w2l = reinterpret_cast<const float*>(smem + SM_W2L);
    const float* s_w2r = reinterpret_cast<const float*>(smem + SM_W2R);
    float p1 = 0.f, q1 = 0.f, p2 = 0.f, q2 = 0.f;
#pragma unroll
    for (int j = 0; j < 16; j++) {
        int c0 = wn * 128 + j * 8 + 2 * tq;
        float v00 = acc[j * 4 + 0] + s_bias[c0];
        float v01 = acc[j * 4 + 1] + s_bias[c0 + 1];
        float v10 = acc[j * 4 + 2] + s_bias[c0];
        float v11 = acc[j * 4 + 3] + s_bias[c0 + 1];
        v00 = v00 > 0.f ? v00 : 0.f;
        v01 = v01 > 0.f ? v01 : 0.f;
        v10 = v10 > 0.f ? v10 : 0.f;
        v11 = v11 > 0.f ? v11 : 0.f;
        p1 = fmaf(v00, s_w2l[c0], fmaf(v01, s_w2l[c0 + 1], p1));
        q1 = fmaf(v00, s_w2r[c0], fmaf(v01, s_w2r[c0 + 1], q1));
        p2 = fmaf(v10, s_w2l[c0], fmaf(v11, s_w2l[c0 + 1], p2));
        q2 = fmaf(v10, s_w2r[c0], fmaf(v11, s_w2r[c0 + 1], q2));
    }
#pragma unroll
    for (int off = 1; off < 4; off <<= 1) {
        p1 += __shfl_xor_sync(0xffffffffu, p1, off);
        q1 += __shfl_xor_sync(0xffffffffu, q1, off);
        p2 += __shfl_xor_sync(0xffffffffu, p2, off);
        q2 += __shfl_xor_sync(0xffffffffu, q2, off);
    }
    float* pbuf = reinterpret_cast<float*>(smem + SM_PQ);           // [2][128]
    float* qbuf = reinterpret_cast<float*>(smem + SM_PQ + 1024);    // [2][128]
    if (tq == 0) {
        int r1 = wm * 16 + g;
        pbuf[wn * 128 + r1] = p1;
        qbuf[wn * 128 + r1] = q1;
        pbuf[wn * 128 + r1 + 8] = p2;
        qbuf[wn * 128 + r1 + 8] = q2;
    }
    __syncthreads();
    if (t < 128) {
        int gr = rowbase + t;
        if (gr < NN) {
            d_p[gr] = pbuf[t] + pbuf[128 + t];
            d_q[gr] = qbuf[t] + qbuf[128 + t];
        }
    }
}

// ---------------- [8] out = mean_agg(p) + b2 + q -----------------------------
__global__ void k_out(const float* __restrict__ b2, float* __restrict__ out) {
    int warp = threadIdx.x >> 5;
    int lane = threadIdx.x & 31;
    int n = blockIdx.x * 8 + warp;
    if (n >= NN) return;

    int s = d_rowptr[n], e = d_rowptr[n + 1];
    float acc = 0.f;
    for (int j = s + lane; j < e; j += 32) acc += d_p[d_csrc[j]];
#pragma unroll
    for (int off = 16; off > 0; off >>= 1)
        acc += __shfl_down_sync(0xffffffffu, acc, off);
    if (lane == 0) {
        int deg = e - s;
        out[n] = acc / (float)max(deg, 1) + b2[0] + d_q[n];
    }
}

// ---------------- launch -----------------------------------------------------
extern "C" void kernel_launch(void* const* d_in, const int* in_sizes, int n_in,
                              void* d_out, int out_size) {
    const float* x    = (const float*)d_in[0];
    const void*  ei   = d_in[1];
    const float* W1l  = (const float*)d_in[2];
    const float* b1   = (const float*)d_in[3];
    const float* W1r  = (const float*)d_in[4];
    const float* W2l  = (const float*)d_in[5];
    const float* b2   = (const float*)d_in[6];
    const float* W2r  = (const float*)d_in[7];
    float* out = (float*)d_out;

    static int attr_set = 0;
    if (!attr_set) {
        cudaFuncSetAttribute(k_gemm, cudaFuncAttributeMaxDynamicSharedMemorySize, SM_TOT);
        attr_set = 1;
    }

    const int nb_scan = (NN + 1023) / 1024;   // 49

    k_init<<<256, 256>>>((const int*)ei, x, W1l, W1r);
    k_count<<<(NE + 255) / 256, 256>>>(ei);
    k_scan1<<<nb_scan, 256>>>();
    k_scan3<<<nb_scan, 1024>>>();
    k_fill<<<(NE + 255) / 256, 256>>>(ei);
    k_agg1<<<(NN + 7) / 8, 256>>>();
    k_gemm<<<(NN + 127) / 128, 512, SM_TOT>>>(b1, W2l, W2r);
    k_out<<<(NN + 7) / 8, 256>>>(b2, out);
}